// round 1
// baseline (speedup 1.0000x reference)
#include <cuda_runtime.h>
#include <math.h>

// SimCLR loss, fused GEMM + streaming logsumexp.
// F = concat(orig, aug) [N=16384, D=128]; sim = F F^T / T; mask diag;
// loss = mean_i( logsumexp_j sim_ij - sim_i,(i+B)%N ).

#define BHALF   8192
#define NTOT    16384
#define DDIM    128
#define BM      64
#define BN      64
#define TPAD    132          // 128 + 4 floats pad: conflict-free LDS.128 across rows
#define NBLK    (NTOT / BM)  // 256

__device__ float g_partials[NBLK];

static __device__ __forceinline__ const float* row_ptr(const float* fo, const float* fa, int r) {
    return (r < BHALF) ? (fo + r * DDIM) : (fa + (r - BHALF) * DDIM);
}

__global__ __launch_bounds__(256, 2)
void simclr_main(const float* __restrict__ fo, const float* __restrict__ fa) {
    extern __shared__ float smbuf[];
    float* As = smbuf;               // [BM][TPAD]
    float* Bs = smbuf + BM * TPAD;   // [BN][TPAD]
    __shared__ float posS[BM];
    __shared__ float red[16];

    const float INV_T = 1.0f / 0.07f;
    const int tid = threadIdx.x;
    const int tx = tid & 15;         // column-group owner
    const int ty = tid >> 4;         // row-group owner
    const int r0 = blockIdx.x * BM;
    const int pos_c0 = (r0 < BHALF) ? (r0 + BHALF) : (r0 - BHALF);

    // Load A tile (64 rows x 128) once. Coalesced float4.
    for (int t = tid; t < BM * (DDIM / 4); t += 256) {
        int row  = t / (DDIM / 4);
        int col4 = t % (DDIM / 4);
        const float* src = row_ptr(fo, fa, r0 + row);
        float4 v = reinterpret_cast<const float4*>(src)[col4];
        reinterpret_cast<float4*>(&As[row * TPAD])[col4] = v;
    }

    float m[4], s[4];
#pragma unroll
    for (int i = 0; i < 4; i++) { m[i] = -1e30f; s[i] = 0.0f; }

    for (int c0 = 0; c0 < NTOT; c0 += BN) {
        __syncthreads();  // Bs consumed by previous iter
        for (int t = tid; t < BN * (DDIM / 4); t += 256) {
            int row  = t / (DDIM / 4);
            int col4 = t % (DDIM / 4);
            const float* src = row_ptr(fo, fa, c0 + row);
            reinterpret_cast<float4*>(&Bs[row * TPAD])[col4] =
                reinterpret_cast<const float4*>(src)[col4];
        }
        __syncthreads();

        // 4x4 micro-tile dot products over k=0..127
        float c[4][4];
#pragma unroll
        for (int i = 0; i < 4; i++)
#pragma unroll
            for (int j = 0; j < 4; j++) c[i][j] = 0.0f;

#pragma unroll 8
        for (int k = 0; k < DDIM; k += 4) {
            float4 av[4], bv[4];
#pragma unroll
            for (int i = 0; i < 4; i++)
                av[i] = *reinterpret_cast<const float4*>(&As[(ty * 4 + i) * TPAD + k]);
#pragma unroll
            for (int j = 0; j < 4; j++)
                bv[j] = *reinterpret_cast<const float4*>(&Bs[(tx * 4 + j) * TPAD + k]);
#pragma unroll
            for (int i = 0; i < 4; i++)
#pragma unroll
                for (int j = 0; j < 4; j++) {
                    c[i][j] = fmaf(av[i].x, bv[j].x, c[i][j]);
                    c[i][j] = fmaf(av[i].y, bv[j].y, c[i][j]);
                    c[i][j] = fmaf(av[i].z, bv[j].z, c[i][j]);
                    c[i][j] = fmaf(av[i].w, bv[j].w, c[i][j]);
                }
        }

#pragma unroll
        for (int i = 0; i < 4; i++)
#pragma unroll
            for (int j = 0; j < 4; j++) c[i][j] *= INV_T;

        // Positive-pair capture and diagonal mask: only threads on the tile
        // diagonal (tx==ty) own (local r, local r) elements.
        if (tx == ty) {
            if (c0 == pos_c0) {
#pragma unroll
                for (int i = 0; i < 4; i++) posS[ty * 4 + i] = c[i][i];
            }
            if (c0 == r0) {
#pragma unroll
                for (int i = 0; i < 4; i++) c[i][i] = -1e30f;  // exp -> exact 0
            }
        }

        // Streaming logsumexp update for this thread's 4 rows x 4 cols
#pragma unroll
        for (int i = 0; i < 4; i++) {
            float tmax = fmaxf(fmaxf(c[i][0], c[i][1]), fmaxf(c[i][2], c[i][3]));
            float nm   = fmaxf(m[i], tmax);
            float acc  = __expf(c[i][0] - nm) + __expf(c[i][1] - nm)
                       + __expf(c[i][2] - nm) + __expf(c[i][3] - nm);
            s[i] = s[i] * __expf(m[i] - nm) + acc;
            m[i] = nm;
        }
    }

    // Merge (m,s) across the 16 threads (tx=0..15) sharing each row.
    // Same-ty threads occupy one contiguous 16-lane half-warp, so xor
    // butterfly with offsets 8..1 stays within the group.
#pragma unroll
    for (int off = 8; off >= 1; off >>= 1) {
#pragma unroll
        for (int i = 0; i < 4; i++) {
            float om = __shfl_xor_sync(0xffffffffu, m[i], off);
            float os = __shfl_xor_sync(0xffffffffu, s[i], off);
            float nm = fmaxf(m[i], om);
            s[i] = s[i] * __expf(m[i] - nm) + os * __expf(om - nm);
            m[i] = nm;
        }
    }

    __syncthreads();  // posS visible to all
    if (tx == 0) {
        float part = 0.0f;
#pragma unroll
        for (int i = 0; i < 4; i++) {
            float lse = m[i] + logf(s[i]);
            part += lse - posS[ty * 4 + i];
        }
        red[ty] = part;
    }
    __syncthreads();
    if (tid == 0) {
        float tot = 0.0f;
#pragma unroll
        for (int i = 0; i < 16; i++) tot += red[i];
        g_partials[blockIdx.x] = tot;
    }
}

__global__ void simclr_final(float* __restrict__ out) {
    __shared__ float red[NBLK];
    red[threadIdx.x] = g_partials[threadIdx.x];
    __syncthreads();
    for (int off = NBLK / 2; off >= 1; off >>= 1) {
        if (threadIdx.x < off) red[threadIdx.x] += red[threadIdx.x + off];
        __syncthreads();
    }
    if (threadIdx.x == 0) out[0] = red[0] / (float)NTOT;
}

extern "C" void kernel_launch(void* const* d_in, const int* in_sizes, int n_in,
                              void* d_out, int out_size) {
    const float* fo = (const float*)d_in[0];
    const float* fa = (const float*)d_in[1];
    float* out = (float*)d_out;

    const int smem_bytes = (BM + BN) * TPAD * (int)sizeof(float);  // 67584
    cudaFuncSetAttribute(simclr_main, cudaFuncAttributeMaxDynamicSharedMemorySize, smem_bytes);

    simclr_main<<<NBLK, 256, smem_bytes>>>(fo, fa);
    simclr_final<<<1, NBLK>>>(out);
}

// round 3
// speedup vs baseline: 8.9438x; 8.9438x over previous
#include <cuda_runtime.h>
#include <cuda_fp16.h>
#include <math.h>
#include <stdint.h>

// ===========================================================================
// SimCLR loss: warp-level HMMA (mma.sync m16n8k16 f16/f32) GEMM fused with an
// online logsumexp, fp16 hi/lo split precision:
//   D = Ahi*Bhi^T + Ahi*Blo^T + Alo*Bhi^T   (fp32 accum, lo*lo dropped ~1e-6)
// F = concat(orig,aug) [16384,128]; sim = F F^T / 0.07; diag masked;
// loss = mean_i( lse_i - sim[i,(i+8192)%16384] ).
// One CTA per 128-row stripe (128 CTAs); loops 128 col-tiles of 128.
// A tile lives in smem all kernel; B double-buffered via cp.async.
// Baseline-ISA only (no tcgen05/TMA): ptxas targets compute_103 (no 'a').
// ===========================================================================

#define BHALF   8192
#define NTOT    16384
#define NT      128
#define NBLK    128
#define THREADS 256

#define B_OFF   65536                   // A: 64KB (hi 32K + lo 32K), then B bufs
#define SMEM_DYN (B_OFF + 2 * 65536)    // 196608

__device__ __align__(16) __half g_hi[NTOT * 128];
__device__ __align__(16) __half g_lo[NTOT * 128];
__device__ float g_partials[NBLK];

// ---------------------------------------------------------------------------
static __device__ __forceinline__ uint32_t smem_u32(const void* p) {
    uint32_t a;
    asm("{ .reg .u64 t; cvta.to.shared.u64 t, %1; cvt.u32.u64 %0, t; }"
        : "=r"(a) : "l"(p));
    return a;
}
static __device__ __forceinline__ float ex2f(float x) {
    float r; asm("ex2.approx.ftz.f32 %0, %1;" : "=f"(r) : "f"(x)); return r;
}
static __device__ __forceinline__ void ldmx4(uint32_t* r, uint32_t addr) {
    asm volatile("ldmatrix.sync.aligned.m8n8.x4.shared.b16 {%0,%1,%2,%3}, [%4];"
                 : "=r"(r[0]), "=r"(r[1]), "=r"(r[2]), "=r"(r[3]) : "r"(addr));
}
static __device__ __forceinline__ void mma16816(float* c, const uint32_t* a,
                                                const uint32_t* b) {
    asm volatile(
        "mma.sync.aligned.m16n8k16.row.col.f32.f16.f16.f32 "
        "{%0,%1,%2,%3}, {%4,%5,%6,%7}, {%8,%9}, {%0,%1,%2,%3};"
        : "+f"(c[0]), "+f"(c[1]), "+f"(c[2]), "+f"(c[3])
        : "r"(a[0]), "r"(a[1]), "r"(a[2]), "r"(a[3]), "r"(b[0]), "r"(b[1]));
}
#define CP_ASYNC16(dst, src) \
    asm volatile("cp.async.cg.shared.global [%0], [%1], 16;" :: "r"(dst), "l"(src) : "memory")
#define CP_COMMIT() asm volatile("cp.async.commit_group;" ::: "memory")
#define CP_WAIT1()  asm volatile("cp.async.wait_group 1;" ::: "memory")
#define CP_WAIT0()  asm volatile("cp.async.wait_group 0;" ::: "memory")

// Load one 128x128 fp16 tile (hi slab 32KB + lo slab 32KB) with XOR swizzle.
// Row stride 256B; 16B chunk c16 stored at (c16 ^ (row&7)).
static __device__ __forceinline__ void load_tile(uint32_t dstBase, int row0, int tid) {
    const char* hb = (const char*)g_hi + (size_t)row0 * 256;
    const char* lb = (const char*)g_lo + (size_t)row0 * 256;
#pragma unroll
    for (int j = 0; j < 16; j++) {
        int q   = tid + j * THREADS;          // 0..4095
        int op  = q >> 11;                    // 0=hi 1=lo
        int idx = q & 2047;
        int row = idx >> 4;
        int c16 = idx & 15;
        uint32_t dst = dstBase + (uint32_t)(op << 15) + (uint32_t)(row << 8)
                     + (uint32_t)(((c16 ^ (row & 7)) << 4));
        const char* src = (op ? lb : hb) + row * 256 + c16 * 16;
        CP_ASYNC16(dst, src);
    }
}

// ---------------------------------------------------------------------------
__global__ void pack_kernel(const float* __restrict__ fo, const float* __restrict__ fa) {
    int idx4 = blockIdx.x * blockDim.x + threadIdx.x;   // float4 units
    int row  = idx4 >> 5;
    const float* src = (row < BHALF) ? fo : fa;
    int lrow = (row < BHALF) ? row : row - BHALF;
    float4 v = reinterpret_cast<const float4*>(src)[(lrow << 5) + (idx4 & 31)];
    float f[4] = {v.x, v.y, v.z, v.w};
    unsigned short hs[4], ls[4];
#pragma unroll
    for (int k = 0; k < 4; k++) {
        __half h = __float2half_rn(f[k]);
        __half l = __float2half_rn(f[k] - __half2float(h));
        hs[k] = __half_as_ushort(h);
        ls[k] = __half_as_ushort(l);
    }
    ushort4 h4 = {hs[0], hs[1], hs[2], hs[3]};
    ushort4 l4 = {ls[0], ls[1], ls[2], ls[3]};
    reinterpret_cast<ushort4*>(g_hi)[idx4] = h4;
    reinterpret_cast<ushort4*>(g_lo)[idx4] = l4;
}

// ---------------------------------------------------------------------------
__global__ __launch_bounds__(THREADS, 1) void simclr_mma() {
    extern __shared__ __align__(1024) char dynsm[];
    __shared__ float sm_m[2][128], sm_s[2][128], sm_pos[128], sm_red[4];

    const uint32_t sbase = smem_u32(dynsm);
    const int tid  = threadIdx.x;
    const int wid  = tid >> 5;
    const int lane = tid & 31;
    const int wy   = wid & 3;    // M chunk (32 rows each)
    const int wx   = wid >> 2;   // N half (64 cols each)
    const int r0   = blockIdx.x * 128;
    const int diag_t = blockIdx.x;
    const int pos_t  = blockIdx.x ^ 64;   // ((r0+8192)%16384)/128

    // ldmatrix address components (A: m16k16 x4; B: two n8k16 per x4)
    const uint32_t a_row  = (uint32_t)(wy * 32 + (lane & 15));
    const uint32_t a_base = sbase + (a_row << 8);
    const uint32_t a_swz  = (a_row & 7) << 4;
    const uint32_t a_koff = (lane >> 4) << 4;          // 0 or 16 bytes

    const uint32_t b_row  = (uint32_t)(wx * 64 + ((lane >> 4) << 3) + (lane & 7));
    const uint32_t b_base = sbase + B_OFF + (b_row << 8);
    const uint32_t b_swz  = (b_row & 7) << 4;
    const uint32_t b_koff = ((lane >> 3) & 1) << 4;    // 0 or 16 bytes

    // Prologue: A stripe (ours, reused all kernel) + B tile 0
    load_tile(sbase, r0, tid);
    load_tile(sbase + B_OFF, 0, tid);
    CP_COMMIT();

    const float C2    = 20.609929155556627f;   // (1/0.07)*log2(e)
    const float LN2   = 0.6931471805599453f;
    const float INV_T = 14.285714285714286f;

    float m[4], s[4];
#pragma unroll
    for (int i = 0; i < 4; i++) { m[i] = -1e30f; s[i] = 0.0f; }

    for (int i = 0; i < NT; i++) {
        if (i + 1 < NT) {
            load_tile(sbase + B_OFF + (uint32_t)(((i + 1) & 1) << 16), (i + 1) << 7, tid);
            CP_COMMIT();
            CP_WAIT1();
        } else {
            CP_WAIT0();
        }
        __syncthreads();

        const uint32_t bbuf = b_base + (uint32_t)((i & 1) << 16);

        float acc[2][8][4];
#pragma unroll
        for (int mi = 0; mi < 2; mi++)
#pragma unroll
            for (int nj = 0; nj < 8; nj++)
#pragma unroll
                for (int k = 0; k < 4; k++) acc[mi][nj][k] = 0.0f;

#pragma unroll 2
        for (int kc = 0; kc < 8; kc++) {
            const uint32_t akx = ((uint32_t)(kc << 5) + a_koff) ^ a_swz;
            const uint32_t bkx = ((uint32_t)(kc << 5) + b_koff) ^ b_swz;
            uint32_t ah[2][4], al[2][4];
#pragma unroll
            for (int mi = 0; mi < 2; mi++) {
                ldmx4(ah[mi], a_base + (uint32_t)(mi << 12) + akx);
                ldmx4(al[mi], a_base + (uint32_t)(mi << 12) + 32768u + akx);
            }
            uint32_t bh[4][4], bl[4][4];
#pragma unroll
            for (int p = 0; p < 4; p++) {
                ldmx4(bh[p], bbuf + (uint32_t)(p << 12) + bkx);
                ldmx4(bl[p], bbuf + (uint32_t)(p << 12) + 32768u + bkx);
            }
#pragma unroll
            for (int mi = 0; mi < 2; mi++)
#pragma unroll
                for (int p = 0; p < 4; p++) {
                    mma16816(acc[mi][2 * p],     ah[mi], &bh[p][0]);
                    mma16816(acc[mi][2 * p + 1], ah[mi], &bh[p][2]);
                    mma16816(acc[mi][2 * p],     ah[mi], &bl[p][0]);
                    mma16816(acc[mi][2 * p + 1], ah[mi], &bl[p][2]);
                    mma16816(acc[mi][2 * p],     al[mi], &bh[p][0]);
                    mma16816(acc[mi][2 * p + 1], al[mi], &bh[p][2]);
                }
        }

        // --- fused epilogue: scale, mask, positive capture, online LSE
        const bool flag = (i == diag_t) | (i == pos_t);
#pragma unroll
        for (int mi = 0; mi < 2; mi++)
#pragma unroll
            for (int rh = 0; rh < 2; rh++) {
                const int ri  = mi * 2 + rh;
                const int r_l = wy * 32 + mi * 16 + rh * 8 + (lane >> 2);
                float y[16];
                if (flag) {
                    const bool isdiag = (i == diag_t);
                    const bool ispos  = (i == pos_t);
#pragma unroll
                    for (int nj = 0; nj < 8; nj++)
#pragma unroll
                        for (int jj = 0; jj < 2; jj++) {
                            const float v = acc[mi][nj][rh * 2 + jj];
                            const int c_l = wx * 64 + nj * 8 + ((lane & 3) << 1) + jj;
                            if (ispos && c_l == r_l) sm_pos[r_l] = v;
                            y[nj * 2 + jj] = (isdiag && c_l == r_l) ? -1e30f : v * C2;
                        }
                } else {
#pragma unroll
                    for (int nj = 0; nj < 8; nj++)
#pragma unroll
                        for (int jj = 0; jj < 2; jj++)
                            y[nj * 2 + jj] = acc[mi][nj][rh * 2 + jj] * C2;
                }
                float mx = y[0];
#pragma unroll
                for (int k = 1; k < 16; k++) mx = fmaxf(mx, y[k]);
                const float nm = fmaxf(m[ri], mx);
                float a0 = 0.0f;
#pragma unroll
                for (int k = 0; k < 16; k++) a0 += ex2f(y[k] - nm);
                s[ri] = s[ri] * ex2f(m[ri] - nm) + a0;
                m[ri] = nm;
            }
        __syncthreads();   // B buffer consumed; safe for next prefetch overwrite
    }

    // --- merge across the 4 lanes sharing each row (lane%4 = column offsets)
#pragma unroll
    for (int off = 1; off <= 2; off <<= 1)
#pragma unroll
        for (int ri = 0; ri < 4; ri++) {
            float om = __shfl_xor_sync(0xffffffffu, m[ri], off);
            float os = __shfl_xor_sync(0xffffffffu, s[ri], off);
            float nm = fmaxf(m[ri], om);
            s[ri] = s[ri] * ex2f(m[ri] - nm) + os * ex2f(om - nm);
            m[ri] = nm;
        }
    if ((lane & 3) == 0) {
#pragma unroll
        for (int mi = 0; mi < 2; mi++)
#pragma unroll
            for (int rh = 0; rh < 2; rh++) {
                const int r_l = wy * 32 + mi * 16 + rh * 8 + (lane >> 2);
                sm_m[wx][r_l] = m[mi * 2 + rh];
                sm_s[wx][r_l] = s[mi * 2 + rh];
            }
    }
    __syncthreads();

    if (tid < 128) {
        const float m0 = sm_m[0][tid], s0 = sm_s[0][tid];
        const float m1 = sm_m[1][tid], s1 = sm_s[1][tid];
        const float nm = fmaxf(m0, m1);
        const float ss = s0 * ex2f(m0 - nm) + s1 * ex2f(m1 - nm);
        const float lse = (nm + log2f(ss)) * LN2;
        float term = lse - sm_pos[tid] * INV_T;
#pragma unroll
        for (int off = 16; off; off >>= 1)
            term += __shfl_xor_sync(0xffffffffu, term, off);
        if ((tid & 31) == 0) sm_red[tid >> 5] = term;
    }
    __syncthreads();
    if (tid == 0)
        g_partials[blockIdx.x] = sm_red[0] + sm_red[1] + sm_red[2] + sm_red[3];
}

__global__ void simclr_final(float* __restrict__ out) {
    __shared__ float red[NBLK];
    red[threadIdx.x] = g_partials[threadIdx.x];
    __syncthreads();
    for (int off = NBLK / 2; off; off >>= 1) {
        if (threadIdx.x < off) red[threadIdx.x] += red[threadIdx.x + off];
        __syncthreads();
    }
    if (threadIdx.x == 0) out[0] = red[0] * (1.0f / (float)NTOT);
}

extern "C" void kernel_launch(void* const* d_in, const int* in_sizes, int n_in,
                              void* d_out, int out_size) {
    const float* fo = (const float*)d_in[0];
    const float* fa = (const float*)d_in[1];
    float* out = (float*)d_out;

    cudaFuncSetAttribute(simclr_mma, cudaFuncAttributeMaxDynamicSharedMemorySize, SMEM_DYN);

    pack_kernel<<<NTOT * 128 / 4 / THREADS, THREADS>>>(fo, fa);
    simclr_mma<<<NBLK, THREADS, SMEM_DYN>>>();
    simclr_final<<<1, NBLK>>>(out);
}

// round 4
// speedup vs baseline: 12.6278x; 1.4119x over previous
#include <cuda_runtime.h>
#include <cuda_fp16.h>
#include <math.h>
#include <stdint.h>

// ===========================================================================
// SimCLR loss: warp-level HMMA (mma.sync m16n8k16 f16/f32) fused with online
// logsumexp. 2-term fp16 split: D = Ahi*Bhi^T + Alo*Bhi^T = A*Bhi^T
// (error a.bl ~2e-2 per logit -> ~1e-4 rel on loss; threshold 1e-3).
// F = concat(orig,aug) [16384,128]; sim = F F^T / 0.07; diag masked;
// loss = mean_i( lse_i - sim[i,(i+8192)%16384] ).
// One CTA per 128-row stripe (128 CTAs); loops 128 col-tiles of 128.
// A (hi+lo, 64KB) resident in smem; B (hi only, 32KB) double-buffered.
// Baseline-ISA only (ptxas targets compute_103, no 'a' -> no tcgen05/TMA).
// ===========================================================================

#define BHALF   8192
#define NTOT    16384
#define NT      128
#define NBLK    128
#define THREADS 256

#define B_OFF   65536                    // A: 64KB (hi 32K + lo 32K)
#define SMEM_DYN (B_OFF + 2 * 32768)     // 131072

__device__ __align__(16) __half g_hi[NTOT * 128];
__device__ __align__(16) __half g_lo[NTOT * 128];
__device__ float g_partials[NBLK];

// ---------------------------------------------------------------------------
static __device__ __forceinline__ uint32_t smem_u32(const void* p) {
    uint32_t a;
    asm("{ .reg .u64 t; cvta.to.shared.u64 t, %1; cvt.u32.u64 %0, t; }"
        : "=r"(a) : "l"(p));
    return a;
}
static __device__ __forceinline__ float ex2f(float x) {
    float r; asm("ex2.approx.ftz.f32 %0, %1;" : "=f"(r) : "f"(x)); return r;
}
static __device__ __forceinline__ void ldmx4(uint32_t* r, uint32_t addr) {
    asm volatile("ldmatrix.sync.aligned.m8n8.x4.shared.b16 {%0,%1,%2,%3}, [%4];"
                 : "=r"(r[0]), "=r"(r[1]), "=r"(r[2]), "=r"(r[3]) : "r"(addr));
}
static __device__ __forceinline__ void mma16816(float* c, const uint32_t* a,
                                                const uint32_t* b) {
    asm volatile(
        "mma.sync.aligned.m16n8k16.row.col.f32.f16.f16.f32 "
        "{%0,%1,%2,%3}, {%4,%5,%6,%7}, {%8,%9}, {%0,%1,%2,%3};"
        : "+f"(c[0]), "+f"(c[1]), "+f"(c[2]), "+f"(c[3])
        : "r"(a[0]), "r"(a[1]), "r"(a[2]), "r"(a[3]), "r"(b[0]), "r"(b[1]));
}
#define CP_ASYNC16(dst, src) \
    asm volatile("cp.async.cg.shared.global [%0], [%1], 16;" :: "r"(dst), "l"(src) : "memory")
#define CP_COMMIT() asm volatile("cp.async.commit_group;" ::: "memory")
#define CP_WAIT1()  asm volatile("cp.async.wait_group 1;" ::: "memory")
#define CP_WAIT0()  asm volatile("cp.async.wait_group 0;" ::: "memory")

// A tile: 128x128 fp16 hi (32KB) + lo (32KB), XOR swizzle (c16 ^ (row&7)).
static __device__ __forceinline__ void load_tile_a(uint32_t dstBase, int row0, int tid) {
    const char* hb = (const char*)g_hi + (size_t)row0 * 256;
    const char* lb = (const char*)g_lo + (size_t)row0 * 256;
#pragma unroll
    for (int j = 0; j < 16; j++) {
        int q   = tid + j * THREADS;          // 0..4095
        int op  = q >> 11;                    // 0=hi 1=lo
        int idx = q & 2047;
        int row = idx >> 4;
        int c16 = idx & 15;
        uint32_t dst = dstBase + (uint32_t)(op << 15) + (uint32_t)(row << 8)
                     + (uint32_t)((c16 ^ (row & 7)) << 4);
        const char* src = (op ? lb : hb) + row * 256 + c16 * 16;
        CP_ASYNC16(dst, src);
    }
}
// B tile: hi only, 32KB.
static __device__ __forceinline__ void load_tile_b(uint32_t dstBase, int row0, int tid) {
    const char* hb = (const char*)g_hi + (size_t)row0 * 256;
#pragma unroll
    for (int j = 0; j < 8; j++) {
        int q   = tid + j * THREADS;          // 0..2047
        int row = q >> 4;
        int c16 = q & 15;
        uint32_t dst = dstBase + (uint32_t)(row << 8)
                     + (uint32_t)((c16 ^ (row & 7)) << 4);
        CP_ASYNC16(dst, hb + row * 256 + c16 * 16);
    }
}

// ---------------------------------------------------------------------------
__global__ void pack_kernel(const float* __restrict__ fo, const float* __restrict__ fa) {
    int idx4 = blockIdx.x * blockDim.x + threadIdx.x;   // float4 units
    int row  = idx4 >> 5;
    const float* src = (row < BHALF) ? fo : fa;
    int lrow = (row < BHALF) ? row : row - BHALF;
    float4 v = reinterpret_cast<const float4*>(src)[(lrow << 5) + (idx4 & 31)];
    float f[4] = {v.x, v.y, v.z, v.w};
    unsigned short hs[4], ls[4];
#pragma unroll
    for (int k = 0; k < 4; k++) {
        __half h = __float2half_rn(f[k]);
        __half l = __float2half_rn(f[k] - __half2float(h));
        hs[k] = __half_as_ushort(h);
        ls[k] = __half_as_ushort(l);
    }
    ushort4 h4 = {hs[0], hs[1], hs[2], hs[3]};
    ushort4 l4 = {ls[0], ls[1], ls[2], ls[3]};
    reinterpret_cast<ushort4*>(g_hi)[idx4] = h4;
    reinterpret_cast<ushort4*>(g_lo)[idx4] = l4;
}

// ---------------------------------------------------------------------------
__global__ __launch_bounds__(THREADS, 1) void simclr_mma() {
    extern __shared__ __align__(1024) char dynsm[];
    __shared__ float sm_m[2][128], sm_s[2][128], sm_pos[128], sm_red[4];

    const uint32_t sbase = smem_u32(dynsm);
    const int tid  = threadIdx.x;
    const int wid  = tid >> 5;
    const int lane = tid & 31;
    const int wy   = wid & 3;    // M chunk (32 rows)
    const int wx   = wid >> 2;   // N half (64 cols)
    const int r0   = blockIdx.x * 128;
    const int diag_t = blockIdx.x;
    const int pos_t  = blockIdx.x ^ 64;   // ((r0+8192)%16384)/128

    const uint32_t a_row  = (uint32_t)(wy * 32 + (lane & 15));
    const uint32_t a_base = sbase + (a_row << 8);
    const uint32_t a_swz  = (a_row & 7) << 4;
    const uint32_t a_koff = (lane >> 4) << 4;

    const uint32_t b_row  = (uint32_t)(wx * 64 + ((lane >> 4) << 3) + (lane & 7));
    const uint32_t b_base = sbase + B_OFF + (b_row << 8);
    const uint32_t b_swz  = (b_row & 7) << 4;
    const uint32_t b_koff = ((lane >> 3) & 1) << 4;

    load_tile_a(sbase, r0, tid);
    load_tile_b(sbase + B_OFF, 0, tid);
    CP_COMMIT();

    const float C2    = 20.609929155556627f;   // (1/0.07)*log2(e)
    const float LN2   = 0.6931471805599453f;
    const float INV_T = 14.285714285714286f;
    const float MASKV = -3.0e28f;               // *C2 stays finite

    float m[4], s[4];
#pragma unroll
    for (int i = 0; i < 4; i++) { m[i] = -1e30f; s[i] = 0.0f; }

    for (int i = 0; i < NT; i++) {
        if (i + 1 < NT) {
            load_tile_b(sbase + B_OFF + (uint32_t)(((i + 1) & 1) << 15), (i + 1) << 7, tid);
            CP_COMMIT();
            CP_WAIT1();
        } else {
            CP_WAIT0();
        }
        __syncthreads();

        const uint32_t bbuf = b_base + (uint32_t)((i & 1) << 15);

        float acc[2][8][4];
#pragma unroll
        for (int mi = 0; mi < 2; mi++)
#pragma unroll
            for (int nj = 0; nj < 8; nj++)
#pragma unroll
                for (int k = 0; k < 4; k++) acc[mi][nj][k] = 0.0f;

#pragma unroll 2
        for (int kc = 0; kc < 8; kc++) {
            const uint32_t akx = ((uint32_t)(kc << 5) + a_koff) ^ a_swz;
            const uint32_t bkx = ((uint32_t)(kc << 5) + b_koff) ^ b_swz;
            uint32_t ah[2][4], al[2][4];
#pragma unroll
            for (int mi = 0; mi < 2; mi++) {
                ldmx4(ah[mi], a_base + (uint32_t)(mi << 12) + akx);
                ldmx4(al[mi], a_base + (uint32_t)(mi << 12) + 32768u + akx);
            }
            uint32_t bh[4][4];
#pragma unroll
            for (int p = 0; p < 4; p++)
                ldmx4(bh[p], bbuf + (uint32_t)(p << 12) + bkx);
#pragma unroll
            for (int mi = 0; mi < 2; mi++)
#pragma unroll
                for (int p = 0; p < 4; p++) {
                    mma16816(acc[mi][2 * p],     ah[mi], &bh[p][0]);
                    mma16816(acc[mi][2 * p + 1], ah[mi], &bh[p][2]);
                    mma16816(acc[mi][2 * p],     al[mi], &bh[p][0]);
                    mma16816(acc[mi][2 * p + 1], al[mi], &bh[p][2]);
                }
        }

        // --- fused epilogue: mask/capture, then online LSE with skip guard
        const bool flag = (i == diag_t) | (i == pos_t);
        if (flag) {
            const bool isdiag = (i == diag_t);
            const bool ispos  = (i == pos_t);
#pragma unroll
            for (int mi = 0; mi < 2; mi++)
#pragma unroll
                for (int rh = 0; rh < 2; rh++) {
                    const int r_l = wy * 32 + mi * 16 + rh * 8 + (lane >> 2);
#pragma unroll
                    for (int nj = 0; nj < 8; nj++)
#pragma unroll
                        for (int jj = 0; jj < 2; jj++) {
                            float& v = acc[mi][nj][rh * 2 + jj];
                            const int c_l = wx * 64 + nj * 8 + ((lane & 3) << 1) + jj;
                            if (ispos && c_l == r_l) sm_pos[r_l] = v;
                            if (isdiag && c_l == r_l) v = MASKV;
                        }
                }
        }
#pragma unroll
        for (int mi = 0; mi < 2; mi++)
#pragma unroll
            for (int rh = 0; rh < 2; rh++) {
                const int ri = mi * 2 + rh;
                float mxr = acc[mi][0][rh * 2];
#pragma unroll
                for (int nj = 0; nj < 8; nj++) {
                    mxr = fmaxf(mxr, acc[mi][nj][rh * 2]);
                    mxr = fmaxf(mxr, acc[mi][nj][rh * 2 + 1]);
                }
                const float mx2 = mxr * C2;
                if (mx2 > m[ri] - 30.0f) {          // skip negligible tiles
                    const float nm = fmaxf(m[ri], mx2);
                    float a0 = 0.0f;
#pragma unroll
                    for (int nj = 0; nj < 8; nj++) {
                        a0 += ex2f(fmaf(acc[mi][nj][rh * 2],     C2, -nm));
                        a0 += ex2f(fmaf(acc[mi][nj][rh * 2 + 1], C2, -nm));
                    }
                    s[ri] = s[ri] * ex2f(m[ri] - nm) + a0;
                    m[ri] = nm;
                }
            }
        __syncthreads();   // B buffer consumed before next prefetch overwrite
    }

    // --- merge across the 4 lanes sharing each row
#pragma unroll
    for (int off = 1; off <= 2; off <<= 1)
#pragma unroll
        for (int ri = 0; ri < 4; ri++) {
            float om = __shfl_xor_sync(0xffffffffu, m[ri], off);
            float os = __shfl_xor_sync(0xffffffffu, s[ri], off);
            float nm = fmaxf(m[ri], om);
            s[ri] = s[ri] * ex2f(m[ri] - nm) + os * ex2f(om - nm);
            m[ri] = nm;
        }
    if ((lane & 3) == 0) {
#pragma unroll
        for (int mi = 0; mi < 2; mi++)
#pragma unroll
            for (int rh = 0; rh < 2; rh++) {
                const int r_l = wy * 32 + mi * 16 + rh * 8 + (lane >> 2);
                sm_m[wx][r_l] = m[mi * 2 + rh];
                sm_s[wx][r_l] = s[mi * 2 + rh];
            }
    }
    __syncthreads();

    if (tid < 128) {
        const float m0 = sm_m[0][tid], s0 = sm_s[0][tid];
        const float m1 = sm_m[1][tid], s1 = sm_s[1][tid];
        const float nm = fmaxf(m0, m1);
        const float ss = s0 * ex2f(m0 - nm) + s1 * ex2f(m1 - nm);
        const float lse = (nm + log2f(ss)) * LN2;
        float term = lse - sm_pos[tid] * INV_T;
#pragma unroll
        for (int off = 16; off; off >>= 1)
            term += __shfl_xor_sync(0xffffffffu, term, off);
        if ((tid & 31) == 0) sm_red[tid >> 5] = term;
    }
    __syncthreads();
    if (tid == 0)
        g_partials[blockIdx.x] = sm_red[0] + sm_red[1] + sm_red[2] + sm_red[3];
}

__global__ void simclr_final(float* __restrict__ out) {
    __shared__ float red[NBLK];
    red[threadIdx.x] = g_partials[threadIdx.x];
    __syncthreads();
    for (int off = NBLK / 2; off; off >>= 1) {
        if (threadIdx.x < off) red[threadIdx.x] += red[threadIdx.x + off];
        __syncthreads();
    }
    if (threadIdx.x == 0) out[0] = red[0] * (1.0f / (float)NTOT);
}

extern "C" void kernel_launch(void* const* d_in, const int* in_sizes, int n_in,
                              void* d_out, int out_size) {
    const float* fo = (const float*)d_in[0];
    const float* fa = (const float*)d_in[1];
    float* out = (float*)d_out;

    cudaFuncSetAttribute(simclr_mma, cudaFuncAttributeMaxDynamicSharedMemorySize, SMEM_DYN);

    pack_kernel<<<NTOT * 128 / 4 / THREADS, THREADS>>>(fo, fa);
    simclr_mma<<<NBLK, THREADS, SMEM_DYN>>>();
    simclr_final<<<1, NBLK>>>(out);
}

// round 5
// speedup vs baseline: 19.2554x; 1.5248x over previous
#include <cuda_runtime.h>
#include <cuda_fp16.h>
#include <math.h>
#include <stdint.h>

// ===========================================================================
// SimCLR loss: warp-level HMMA (mma.sync m16n8k16 f16/f32) fused with online
// logsumexp. Pure fp16 single-term: D = Ahi*Bhi^T (fp32 accumulate).
// Per-logit error ~0.03 logit units averages down ~sqrt(16384) in the row-mean
// loss -> measured-model rel_err ~ few e-6 (threshold 1e-3).
// F = concat(orig,aug) [16384,128]; sim = F F^T / 0.07; diag masked;
// loss = mean_i( lse_i - sim[i,(i+8192)%16384] ).
// One CTA per 128-row stripe (128 CTAs); loops 128 col-tiles of 128.
// A (hi, 32KB) resident in smem; B (hi, 32KB) double-buffered via cp.async.
// Baseline-ISA only (ptxas targets compute_103, no 'a' -> no tcgen05/TMA).
// ===========================================================================

#define BHALF   8192
#define NTOT    16384
#define NT      128
#define NBLK    128
#define THREADS 256

#define B_OFF   32768                    // A: 32KB hi
#define SMEM_DYN (B_OFF + 2 * 32768)     // 98304

__device__ __align__(16) __half g_hi[NTOT * 128];
__device__ float g_partials[NBLK];

// ---------------------------------------------------------------------------
static __device__ __forceinline__ uint32_t smem_u32(const void* p) {
    uint32_t a;
    asm("{ .reg .u64 t; cvta.to.shared.u64 t, %1; cvt.u32.u64 %0, t; }"
        : "=r"(a) : "l"(p));
    return a;
}
static __device__ __forceinline__ float ex2f(float x) {
    float r; asm("ex2.approx.ftz.f32 %0, %1;" : "=f"(r) : "f"(x)); return r;
}
static __device__ __forceinline__ void ldmx4(uint32_t* r, uint32_t addr) {
    asm volatile("ldmatrix.sync.aligned.m8n8.x4.shared.b16 {%0,%1,%2,%3}, [%4];"
                 : "=r"(r[0]), "=r"(r[1]), "=r"(r[2]), "=r"(r[3]) : "r"(addr));
}
static __device__ __forceinline__ void mma16816(float* c, const uint32_t* a,
                                                const uint32_t* b) {
    asm volatile(
        "mma.sync.aligned.m16n8k16.row.col.f32.f16.f16.f32 "
        "{%0,%1,%2,%3}, {%4,%5,%6,%7}, {%8,%9}, {%0,%1,%2,%3};"
        : "+f"(c[0]), "+f"(c[1]), "+f"(c[2]), "+f"(c[3])
        : "r"(a[0]), "r"(a[1]), "r"(a[2]), "r"(a[3]), "r"(b[0]), "r"(b[1]));
}
#define CP_ASYNC16(dst, src) \
    asm volatile("cp.async.cg.shared.global [%0], [%1], 16;" :: "r"(dst), "l"(src) : "memory")
#define CP_COMMIT() asm volatile("cp.async.commit_group;" ::: "memory")
#define CP_WAIT1()  asm volatile("cp.async.wait_group 1;" ::: "memory")
#define CP_WAIT0()  asm volatile("cp.async.wait_group 0;" ::: "memory")

// One 128x128 fp16 tile (32KB), XOR swizzle (c16 ^ (row&7)) -> conflict-free
// ldmatrix and conflict-free cp.async stores.
static __device__ __forceinline__ void load_tile(uint32_t dstBase, int row0, int tid) {
    const char* hb = (const char*)g_hi + (size_t)row0 * 256;
#pragma unroll
    for (int j = 0; j < 8; j++) {
        int q   = tid + j * THREADS;          // 0..2047
        int row = q >> 4;
        int c16 = q & 15;
        uint32_t dst = dstBase + (uint32_t)(row << 8)
                     + (uint32_t)((c16 ^ (row & 7)) << 4);
        CP_ASYNC16(dst, hb + row * 256 + c16 * 16);
    }
}

// ---------------------------------------------------------------------------
__global__ void pack_kernel(const float* __restrict__ fo, const float* __restrict__ fa) {
    int idx4 = blockIdx.x * blockDim.x + threadIdx.x;   // float4 units
    int row  = idx4 >> 5;
    const float* src = (row < BHALF) ? fo : fa;
    int lrow = (row < BHALF) ? row : row - BHALF;
    float4 v = reinterpret_cast<const float4*>(src)[(lrow << 5) + (idx4 & 31)];
    ushort4 h4;
    h4.x = __half_as_ushort(__float2half_rn(v.x));
    h4.y = __half_as_ushort(__float2half_rn(v.y));
    h4.z = __half_as_ushort(__float2half_rn(v.z));
    h4.w = __half_as_ushort(__float2half_rn(v.w));
    reinterpret_cast<ushort4*>(g_hi)[idx4] = h4;
}

// ---------------------------------------------------------------------------
__global__ __launch_bounds__(THREADS, 1) void simclr_mma() {
    extern __shared__ __align__(1024) char dynsm[];
    __shared__ float sm_m[2][128], sm_s[2][128], sm_pos[128], sm_red[4];

    const uint32_t sbase = smem_u32(dynsm);
    const int tid  = threadIdx.x;
    const int wid  = tid >> 5;
    const int lane = tid & 31;
    const int wy   = wid & 3;    // M chunk (32 rows)
    const int wx   = wid >> 2;   // N half (64 cols)
    const int r0   = blockIdx.x * 128;
    const int diag_t = blockIdx.x;
    const int pos_t  = blockIdx.x ^ 64;   // ((r0+8192)%16384)/128

    const uint32_t a_row  = (uint32_t)(wy * 32 + (lane & 15));
    const uint32_t a_base = sbase + (a_row << 8);
    const uint32_t a_swz  = (a_row & 7) << 4;
    const uint32_t a_koff = (lane >> 4) << 4;

    const uint32_t b_row  = (uint32_t)(wx * 64 + ((lane >> 4) << 3) + (lane & 7));
    const uint32_t b_base = sbase + B_OFF + (b_row << 8);
    const uint32_t b_swz  = (b_row & 7) << 4;
    const uint32_t b_koff = ((lane >> 3) & 1) << 4;

    load_tile(sbase, r0, tid);           // A stripe, resident all kernel
    load_tile(sbase + B_OFF, 0, tid);    // B tile 0
    CP_COMMIT();

    const float C2    = 20.609929155556627f;   // (1/0.07)*log2(e)
    const float LN2   = 0.6931471805599453f;
    const float INV_T = 14.285714285714286f;
    const float MASKV = -3.0e28f;               // *C2 stays finite

    float m[4], s[4];
#pragma unroll
    for (int i = 0; i < 4; i++) { m[i] = -1e30f; s[i] = 0.0f; }

    for (int i = 0; i < NT; i++) {
        if (i + 1 < NT) {
            load_tile(sbase + B_OFF + (uint32_t)(((i + 1) & 1) << 15), (i + 1) << 7, tid);
            CP_COMMIT();
            CP_WAIT1();
        } else {
            CP_WAIT0();
        }
        __syncthreads();

        const uint32_t bbuf = b_base + (uint32_t)((i & 1) << 15);

        float acc[2][8][4];
#pragma unroll
        for (int mi = 0; mi < 2; mi++)
#pragma unroll
            for (int nj = 0; nj < 8; nj++)
#pragma unroll
                for (int k = 0; k < 4; k++) acc[mi][nj][k] = 0.0f;

#pragma unroll 4
        for (int kc = 0; kc < 8; kc++) {
            const uint32_t akx = ((uint32_t)(kc << 5) + a_koff) ^ a_swz;
            const uint32_t bkx = ((uint32_t)(kc << 5) + b_koff) ^ b_swz;
            uint32_t ah[2][4];
#pragma unroll
            for (int mi = 0; mi < 2; mi++)
                ldmx4(ah[mi], a_base + (uint32_t)(mi << 12) + akx);
            uint32_t bh[4][4];
#pragma unroll
            for (int p = 0; p < 4; p++)
                ldmx4(bh[p], bbuf + (uint32_t)(p << 12) + bkx);
#pragma unroll
            for (int mi = 0; mi < 2; mi++)
#pragma unroll
                for (int p = 0; p < 4; p++) {
                    mma16816(acc[mi][2 * p],     ah[mi], &bh[p][0]);
                    mma16816(acc[mi][2 * p + 1], ah[mi], &bh[p][2]);
                }
        }

        // --- fused epilogue: mask/capture, then online LSE with skip guard
        if ((i == diag_t) | (i == pos_t)) {
            const bool isdiag = (i == diag_t);
            const bool ispos  = (i == pos_t);
#pragma unroll
            for (int mi = 0; mi < 2; mi++)
#pragma unroll
                for (int rh = 0; rh < 2; rh++) {
                    const int r_l = wy * 32 + mi * 16 + rh * 8 + (lane >> 2);
#pragma unroll
                    for (int nj = 0; nj < 8; nj++)
#pragma unroll
                        for (int jj = 0; jj < 2; jj++) {
                            float& v = acc[mi][nj][rh * 2 + jj];
                            const int c_l = wx * 64 + nj * 8 + ((lane & 3) << 1) + jj;
                            if (ispos && c_l == r_l) sm_pos[r_l] = v;
                            if (isdiag && c_l == r_l) v = MASKV;
                        }
                }
        }
#pragma unroll
        for (int mi = 0; mi < 2; mi++)
#pragma unroll
            for (int rh = 0; rh < 2; rh++) {
                const int ri = mi * 2 + rh;
                float mxr = acc[mi][0][rh * 2];
#pragma unroll
                for (int nj = 0; nj < 8; nj++) {
                    mxr = fmaxf(mxr, acc[mi][nj][rh * 2]);
                    mxr = fmaxf(mxr, acc[mi][nj][rh * 2 + 1]);
                }
                const float mx2 = mxr * C2;
                if (mx2 > m[ri] - 30.0f) {          // tiles with negligible mass
                    const float nm = fmaxf(m[ri], mx2);
                    float a0 = 0.0f;
#pragma unroll
                    for (int nj = 0; nj < 8; nj++) {
                        a0 += ex2f(fmaf(acc[mi][nj][rh * 2],     C2, -nm));
                        a0 += ex2f(fmaf(acc[mi][nj][rh * 2 + 1], C2, -nm));
                    }
                    s[ri] = s[ri] * ex2f(m[ri] - nm) + a0;
                    m[ri] = nm;
                }
            }
        __syncthreads();   // B buffer consumed before next prefetch overwrite
    }

    // --- merge across the 4 lanes sharing each row
#pragma unroll
    for (int off = 1; off <= 2; off <<= 1)
#pragma unroll
        for (int ri = 0; ri < 4; ri++) {
            float om = __shfl_xor_sync(0xffffffffu, m[ri], off);
            float os = __shfl_xor_sync(0xffffffffu, s[ri], off);
            float nm = fmaxf(m[ri], om);
            s[ri] = s[ri] * ex2f(m[ri] - nm) + os * ex2f(om - nm);
            m[ri] = nm;
        }
    if ((lane & 3) == 0) {
#pragma unroll
        for (int mi = 0; mi < 2; mi++)
#pragma unroll
            for (int rh = 0; rh < 2; rh++) {
                const int r_l = wy * 32 + mi * 16 + rh * 8 + (lane >> 2);
                sm_m[wx][r_l] = m[mi * 2 + rh];
                sm_s[wx][r_l] = s[mi * 2 + rh];
            }
    }
    __syncthreads();

    if (tid < 128) {
        const float m0 = sm_m[0][tid], s0 = sm_s[0][tid];
        const float m1 = sm_m[1][tid], s1 = sm_s[1][tid];
        const float nm = fmaxf(m0, m1);
        const float ss = s0 * ex2f(m0 - nm) + s1 * ex2f(m1 - nm);
        const float lse = (nm + log2f(ss)) * LN2;
        float term = lse - sm_pos[tid] * INV_T;
#pragma unroll
        for (int off = 16; off; off >>= 1)
            term += __shfl_xor_sync(0xffffffffu, term, off);
        if ((tid & 31) == 0) sm_red[tid >> 5] = term;
    }
    __syncthreads();
    if (tid == 0)
        g_partials[blockIdx.x] = sm_red[0] + sm_red[1] + sm_red[2] + sm_red[3];
}

__global__ void simclr_final(float* __restrict__ out) {
    __shared__ float red[NBLK];
    red[threadIdx.x] = g_partials[threadIdx.x];
    __syncthreads();
    for (int off = NBLK / 2; off; off >>= 1) {
        if (threadIdx.x < off) red[threadIdx.x] += red[threadIdx.x + off];
        __syncthreads();
    }
    if (threadIdx.x == 0) out[0] = red[0] * (1.0f / (float)NTOT);
}

extern "C" void kernel_launch(void* const* d_in, const int* in_sizes, int n_in,
                              void* d_out, int out_size) {
    const float* fo = (const float*)d_in[0];
    const float* fa = (const float*)d_in[1];
    float* out = (float*)d_out;

    cudaFuncSetAttribute(simclr_mma, cudaFuncAttributeMaxDynamicSharedMemorySize, SMEM_DYN);

    pack_kernel<<<NTOT * 128 / 4 / THREADS, THREADS>>>(fo, fa);
    simclr_mma<<<NBLK, THREADS, SMEM_DYN>>>();
    simclr_final<<<1, NBLK>>>(out);
}

// round 6
// speedup vs baseline: 23.2803x; 1.2090x over previous
#include <cuda_runtime.h>
#include <cuda_fp16.h>
#include <math.h>
#include <stdint.h>

// ===========================================================================
// SimCLR loss, symmetry-halved HMMA GEMM + fused two-sided online logsumexp.
// sim = F F^T / T is symmetric: tile (i,j) computed ONCE feeds stripe-i rows
// (row-wise LSE, register state) and stripe-j rows (column-wise LSE, per-warp
// (m,s) partials to global scratch). CTA i handles d=0..63 (j=(i+d)&127),
// plus d=64 iff i<64  -> 8256 of 16384 tiles. Merge kernel combines partials.
// Pure fp16 single-term: D = Ahi*Bhi^T, fp32 accum (measured loss rel_err
// ~8e-7 at threshold 1e-3). Baseline ISA only (compute_103: no tcgen05/TMA).
// ===========================================================================

#define BHALF   8192
#define NTOT    16384
#define NBLK    128
#define THREADS 256

#define B_OFF   32768                    // A: 32KB hi
#define SMEM_DYN (B_OFF + 2 * 32768)     // 98304

__device__ __align__(16) __half g_hi[NTOT * 128];
__device__ float2 g_cp[128 * 65 * 4 * 128];   // [stripe j][d][wy][col] col partials
__device__ float2 g_rp[NTOT];                 // per-row register partial (m,s)
__device__ float  g_pos[NTOT];                // raw positive dot per row
__device__ float  g_partials[NBLK];

// ---------------------------------------------------------------------------
static __device__ __forceinline__ uint32_t smem_u32(const void* p) {
    uint32_t a;
    asm("{ .reg .u64 t; cvta.to.shared.u64 t, %1; cvt.u32.u64 %0, t; }"
        : "=r"(a) : "l"(p));
    return a;
}
static __device__ __forceinline__ float ex2f(float x) {
    float r; asm("ex2.approx.ftz.f32 %0, %1;" : "=f"(r) : "f"(x)); return r;
}
static __device__ __forceinline__ void ldmx4(uint32_t* r, uint32_t addr) {
    asm volatile("ldmatrix.sync.aligned.m8n8.x4.shared.b16 {%0,%1,%2,%3}, [%4];"
                 : "=r"(r[0]), "=r"(r[1]), "=r"(r[2]), "=r"(r[3]) : "r"(addr));
}
static __device__ __forceinline__ void mma16816(float* c, const uint32_t* a,
                                                const uint32_t* b) {
    asm volatile(
        "mma.sync.aligned.m16n8k16.row.col.f32.f16.f16.f32 "
        "{%0,%1,%2,%3}, {%4,%5,%6,%7}, {%8,%9}, {%0,%1,%2,%3};"
        : "+f"(c[0]), "+f"(c[1]), "+f"(c[2]), "+f"(c[3])
        : "r"(a[0]), "r"(a[1]), "r"(a[2]), "r"(a[3]), "r"(b[0]), "r"(b[1]));
}
// single-ex2 (m,s) merge
static __device__ __forceinline__ void msmerge(float& m, float& s, float om, float os) {
    float dm = m - om;
    float e  = ex2f(-fabsf(dm));
    s = (dm >= 0.0f) ? fmaf(os, e, s) : fmaf(s, e, os);
    m = fmaxf(m, om);
}
#define CP_ASYNC16(dst, src) \
    asm volatile("cp.async.cg.shared.global [%0], [%1], 16;" :: "r"(dst), "l"(src) : "memory")
#define CP_COMMIT() asm volatile("cp.async.commit_group;" ::: "memory")
#define CP_WAIT1()  asm volatile("cp.async.wait_group 1;" ::: "memory")
#define CP_WAIT0()  asm volatile("cp.async.wait_group 0;" ::: "memory")

// One 128x128 fp16 tile (32KB), XOR swizzle (c16 ^ (row&7)).
static __device__ __forceinline__ void load_tile(uint32_t dstBase, int row0, int tid) {
    const char* hb = (const char*)g_hi + (size_t)row0 * 256;
#pragma unroll
    for (int j = 0; j < 8; j++) {
        int q   = tid + j * THREADS;          // 0..2047
        int row = q >> 4;
        int c16 = q & 15;
        uint32_t dst = dstBase + (uint32_t)(row << 8)
                     + (uint32_t)((c16 ^ (row & 7)) << 4);
        CP_ASYNC16(dst, hb + row * 256 + c16 * 16);
    }
}

// ---------------------------------------------------------------------------
__global__ void pack_kernel(const float* __restrict__ fo, const float* __restrict__ fa) {
    int idx4 = blockIdx.x * blockDim.x + threadIdx.x;
    int row  = idx4 >> 5;
    const float* src = (row < BHALF) ? fo : fa;
    int lrow = (row < BHALF) ? row : row - BHALF;
    float4 v = reinterpret_cast<const float4*>(src)[(lrow << 5) + (idx4 & 31)];
    ushort4 h4;
    h4.x = __half_as_ushort(__float2half_rn(v.x));
    h4.y = __half_as_ushort(__float2half_rn(v.y));
    h4.z = __half_as_ushort(__float2half_rn(v.z));
    h4.w = __half_as_ushort(__float2half_rn(v.w));
    reinterpret_cast<ushort4*>(g_hi)[idx4] = h4;
}

// ---------------------------------------------------------------------------
__global__ __launch_bounds__(THREADS, 1) void simclr_mma() {
    extern __shared__ __align__(1024) char dynsm[];
    __shared__ float sm_m[2][128], sm_s[2][128];

    const uint32_t sbase = smem_u32(dynsm);
    const int tid  = threadIdx.x;
    const int wid  = tid >> 5;
    const int lane = tid & 31;
    const int wy   = wid & 3;    // M chunk (32 rows)
    const int wx   = wid >> 2;   // N half (64 cols)
    const int bid  = blockIdx.x;
    const int r0   = bid * 128;
    const int dmax = (bid < 64) ? 64 : 63;

    const uint32_t a_row  = (uint32_t)(wy * 32 + (lane & 15));
    const uint32_t a_base = sbase + (a_row << 8);
    const uint32_t a_swz  = (a_row & 7) << 4;
    const uint32_t a_koff = (lane >> 4) << 4;

    const uint32_t b_row  = (uint32_t)(wx * 64 + ((lane >> 4) << 3) + (lane & 7));
    const uint32_t b_base = sbase + B_OFF + (b_row << 8);
    const uint32_t b_swz  = (b_row & 7) << 4;
    const uint32_t b_koff = ((lane >> 3) & 1) << 4;

    load_tile(sbase, r0, tid);           // A stripe, resident all kernel
    load_tile(sbase + B_OFF, r0, tid);   // B tile d=0 (j=i)
    CP_COMMIT();

    const float C2    = 20.609929155556627f;   // (1/0.07)*log2(e)
    const float MASKV = -3.0e28f;

    float m[4], s[4];
#pragma unroll
    for (int i = 0; i < 4; i++) { m[i] = -1e30f; s[i] = 0.0f; }

    for (int d = 0; d <= dmax; d++) {
        const int j = (bid + d) & 127;
        if (d < dmax) {
            load_tile(sbase + B_OFF + (uint32_t)(((d + 1) & 1) << 15),
                      ((bid + d + 1) & 127) << 7, tid);
            CP_COMMIT();
            CP_WAIT1();
        } else {
            CP_WAIT0();
        }
        __syncthreads();

        const uint32_t bbuf = b_base + (uint32_t)((d & 1) << 15);

        float acc[2][8][4];
#pragma unroll
        for (int mi = 0; mi < 2; mi++)
#pragma unroll
            for (int nj = 0; nj < 8; nj++)
#pragma unroll
                for (int k = 0; k < 4; k++) acc[mi][nj][k] = 0.0f;

#pragma unroll 4
        for (int kc = 0; kc < 8; kc++) {
            const uint32_t akx = ((uint32_t)(kc << 5) + a_koff) ^ a_swz;
            const uint32_t bkx = ((uint32_t)(kc << 5) + b_koff) ^ b_swz;
            uint32_t ah[2][4];
#pragma unroll
            for (int mi = 0; mi < 2; mi++)
                ldmx4(ah[mi], a_base + (uint32_t)(mi << 12) + akx);
            uint32_t bh[4][4];
#pragma unroll
            for (int p = 0; p < 4; p++)
                ldmx4(bh[p], bbuf + (uint32_t)(p << 12) + bkx);
#pragma unroll
            for (int mi = 0; mi < 2; mi++)
#pragma unroll
                for (int p = 0; p < 4; p++) {
                    mma16816(acc[mi][2 * p],     ah[mi], &bh[p][0]);
                    mma16816(acc[mi][2 * p + 1], ah[mi], &bh[p][2]);
                }
        }

        // --- diag mask (d==0) / positive capture (d==64, serves both stripes)
        if ((d == 0) | (d == 64)) {
            const bool isdiag = (d == 0);
#pragma unroll
            for (int mi = 0; mi < 2; mi++)
#pragma unroll
                for (int rh = 0; rh < 2; rh++) {
                    const int r_l = wy * 32 + mi * 16 + rh * 8 + (lane >> 2);
#pragma unroll
                    for (int nj = 0; nj < 8; nj++)
#pragma unroll
                        for (int jj = 0; jj < 2; jj++) {
                            float& v = acc[mi][nj][rh * 2 + jj];
                            const int c_l = wx * 64 + nj * 8 + ((lane & 3) << 1) + jj;
                            if (c_l == r_l) {
                                if (isdiag) v = MASKV;
                                else {
                                    g_pos[(bid << 7) + r_l] = v;
                                    g_pos[(j << 7) + r_l]   = v;
                                }
                            }
                        }
                }
        }

        // --- row-side online LSE (register state) with skip guard
#pragma unroll
        for (int mi = 0; mi < 2; mi++)
#pragma unroll
            for (int rh = 0; rh < 2; rh++) {
                const int ri = mi * 2 + rh;
                float mxr = acc[mi][0][rh * 2];
#pragma unroll
                for (int nj = 0; nj < 8; nj++) {
                    mxr = fmaxf(mxr, acc[mi][nj][rh * 2]);
                    mxr = fmaxf(mxr, acc[mi][nj][rh * 2 + 1]);
                }
                const float mx2 = mxr * C2;
                if (mx2 > m[ri] - 30.0f) {
                    const float nm = fmaxf(m[ri], mx2);
                    float a0 = 0.0f;
#pragma unroll
                    for (int nj = 0; nj < 8; nj++) {
                        a0 += ex2f(fmaf(acc[mi][nj][rh * 2],     C2, -nm));
                        a0 += ex2f(fmaf(acc[mi][nj][rh * 2 + 1], C2, -nm));
                    }
                    s[ri] = s[ri] * ex2f(m[ri] - nm) + a0;
                    m[ri] = nm;
                }
            }

        // --- column-side partials for stripe j (skip self tile d==0)
        if (d != 0) {
            float cm[16], cs[16];
#pragma unroll
            for (int nj = 0; nj < 8; nj++)
#pragma unroll
                for (int jj = 0; jj < 2; jj++) {
                    const int q = nj * 2 + jj;
                    const float v0 = acc[0][nj][jj],     v1 = acc[0][nj][2 + jj];
                    const float v2 = acc[1][nj][jj],     v3 = acc[1][nj][2 + jj];
                    const float mx = fmaxf(fmaxf(v0, v1), fmaxf(v2, v3)) * C2;
                    cm[q] = mx;
                    cs[q] = ex2f(fmaf(v0, C2, -mx)) + ex2f(fmaf(v1, C2, -mx))
                          + ex2f(fmaf(v2, C2, -mx)) + ex2f(fmaf(v3, C2, -mx));
                }
#pragma unroll
            for (int off = 4; off <= 16; off <<= 1)
#pragma unroll
                for (int q = 0; q < 16; q++) {
                    const float om = __shfl_xor_sync(0xffffffffu, cm[q], off);
                    const float os = __shfl_xor_sync(0xffffffffu, cs[q], off);
                    msmerge(cm[q], cs[q], om, os);
                }
            if (lane < 4) {
                const int slotBase = (((j * 65 + d) << 2) + wy) * 128 + wx * 64;
#pragma unroll
                for (int nj = 0; nj < 8; nj++)
#pragma unroll
                    for (int jj = 0; jj < 2; jj++) {
                        const int c = nj * 8 + lane * 2 + jj;
                        g_cp[slotBase + c] = make_float2(cm[nj * 2 + jj], cs[nj * 2 + jj]);
                    }
            }
        }
        __syncthreads();   // B buffer consumed before next prefetch overwrite
    }

    // --- merge row state across the 4 lanes sharing each row, write g_rp
#pragma unroll
    for (int off = 1; off <= 2; off <<= 1)
#pragma unroll
        for (int ri = 0; ri < 4; ri++) {
            const float om = __shfl_xor_sync(0xffffffffu, m[ri], off);
            const float os = __shfl_xor_sync(0xffffffffu, s[ri], off);
            msmerge(m[ri], s[ri], om, os);
        }
    if ((lane & 3) == 0) {
#pragma unroll
        for (int mi = 0; mi < 2; mi++)
#pragma unroll
            for (int rh = 0; rh < 2; rh++) {
                const int r_l = wy * 32 + mi * 16 + rh * 8 + (lane >> 2);
                sm_m[wx][r_l] = m[mi * 2 + rh];
                sm_s[wx][r_l] = s[mi * 2 + rh];
            }
    }
    __syncthreads();
    if (tid < 128) {
        float mm = sm_m[0][tid], ss = sm_s[0][tid];
        msmerge(mm, ss, sm_m[1][tid], sm_s[1][tid]);
        g_rp[(bid << 7) + tid] = make_float2(mm, ss);
    }
}

// ---------------------------------------------------------------------------
// Merge kernel: per row, combine register row-partial + col partials.
__global__ __launch_bounds__(128) void simclr_merge() {
    __shared__ float red[4];
    const int r   = blockIdx.x;
    const int k   = threadIdx.x;      // row within stripe
    const int dmx = (r >= 64) ? 64 : 63;

    // 4 independent chains (one per wy) to hide MUFU latency
    float mm[4], ss[4];
    {
        const float2 p0 = g_cp[(((r * 65 + 1) << 2) + 0) * 128 + k];
        const float2 p1 = g_cp[(((r * 65 + 1) << 2) + 1) * 128 + k];
        const float2 p2 = g_cp[(((r * 65 + 1) << 2) + 2) * 128 + k];
        const float2 p3 = g_cp[(((r * 65 + 1) << 2) + 3) * 128 + k];
        mm[0] = p0.x; ss[0] = p0.y;  mm[1] = p1.x; ss[1] = p1.y;
        mm[2] = p2.x; ss[2] = p2.y;  mm[3] = p3.x; ss[3] = p3.y;
    }
    for (int d = 2; d <= dmx; d++) {
#pragma unroll
        for (int w = 0; w < 4; w++) {
            const float2 p = g_cp[(((r * 65 + d) << 2) + w) * 128 + k];
            msmerge(mm[w], ss[w], p.x, p.y);
        }
    }
    msmerge(mm[0], ss[0], mm[1], ss[1]);
    msmerge(mm[2], ss[2], mm[3], ss[3]);
    msmerge(mm[0], ss[0], mm[2], ss[2]);
    const float2 rp = g_rp[(r << 7) + k];
    msmerge(mm[0], ss[0], rp.x, rp.y);

    const float LN2   = 0.6931471805599453f;
    const float INV_T = 14.285714285714286f;
    const float lse   = (mm[0] + log2f(ss[0])) * LN2;
    float term = lse - g_pos[(r << 7) + k] * INV_T;
#pragma unroll
    for (int off = 16; off; off >>= 1)
        term += __shfl_xor_sync(0xffffffffu, term, off);
    if ((k & 31) == 0) red[k >> 5] = term;
    __syncthreads();
    if (k == 0) g_partials[r] = red[0] + red[1] + red[2] + red[3];
}

__global__ void simclr_final(float* __restrict__ out) {
    __shared__ float red[NBLK];
    red[threadIdx.x] = g_partials[threadIdx.x];
    __syncthreads();
    for (int off = NBLK / 2; off; off >>= 1) {
        if (threadIdx.x < off) red[threadIdx.x] += red[threadIdx.x + off];
        __syncthreads();
    }
    if (threadIdx.x == 0) out[0] = red[0] * (1.0f / (float)NTOT);
}

extern "C" void kernel_launch(void* const* d_in, const int* in_sizes, int n_in,
                              void* d_out, int out_size) {
    const float* fo = (const float*)d_in[0];
    const float* fa = (const float*)d_in[1];
    float* out = (float*)d_out;

    cudaFuncSetAttribute(simclr_mma, cudaFuncAttributeMaxDynamicSharedMemorySize, SMEM_DYN);

    pack_kernel<<<NTOT * 128 / 4 / THREADS, THREADS>>>(fo, fa);
    simclr_mma<<<NBLK, THREADS, SMEM_DYN>>>();
    simclr_merge<<<NBLK, 128>>>();
    simclr_final<<<1, NBLK>>>(out);
}

// round 7
// speedup vs baseline: 24.8465x; 1.0673x over previous
#include <cuda_runtime.h>
#include <cuda_fp16.h>
#include <math.h>
#include <stdint.h>

// ===========================================================================
// SimCLR loss, symmetry-halved HMMA GEMM + fused two-sided online logsumexp,
// SOFTWARE-PIPELINED epilogue: tile d's MMAs issue into accCur while tile
// d-1's epilogue (MUFU/fma/shfl, different pipes) runs from accPrev under the
// tensor-pipe shadow. Col-side reduction split into max-reduce then
// sum-reduce (4 ex2/col instead of 7).
// Pure fp16 single-term D = Ahi*Bhi^T (measured loss rel_err ~8e-7).
// Baseline ISA only (compute_103: no tcgen05/TMA).
// ===========================================================================

#define BHALF   8192
#define NTOT    16384
#define NBLK    128
#define THREADS 256

#define B_OFF   32768
#define SMEM_DYN (B_OFF + 2 * 32768)     // 98304

__device__ __align__(16) __half g_hi[NTOT * 128];
__device__ float2 g_cp[128 * 65 * 4 * 128];   // [stripe j][d][wy][col]
__device__ float2 g_rp[NTOT];
__device__ float  g_pos[NTOT];
__device__ float  g_partials[NBLK];

// ---------------------------------------------------------------------------
static __device__ __forceinline__ uint32_t smem_u32(const void* p) {
    uint32_t a;
    asm("{ .reg .u64 t; cvta.to.shared.u64 t, %1; cvt.u32.u64 %0, t; }"
        : "=r"(a) : "l"(p));
    return a;
}
static __device__ __forceinline__ float ex2f(float x) {
    float r; asm("ex2.approx.ftz.f32 %0, %1;" : "=f"(r) : "f"(x)); return r;
}
static __device__ __forceinline__ void ldmx4(uint32_t* r, uint32_t addr) {
    asm volatile("ldmatrix.sync.aligned.m8n8.x4.shared.b16 {%0,%1,%2,%3}, [%4];"
                 : "=r"(r[0]), "=r"(r[1]), "=r"(r[2]), "=r"(r[3]) : "r"(addr));
}
static __device__ __forceinline__ void mma16816(float* c, const uint32_t* a,
                                                const uint32_t* b) {
    asm volatile(
        "mma.sync.aligned.m16n8k16.row.col.f32.f16.f16.f32 "
        "{%0,%1,%2,%3}, {%4,%5,%6,%7}, {%8,%9}, {%0,%1,%2,%3};"
        : "+f"(c[0]), "+f"(c[1]), "+f"(c[2]), "+f"(c[3])
        : "r"(a[0]), "r"(a[1]), "r"(a[2]), "r"(a[3]), "r"(b[0]), "r"(b[1]));
}
static __device__ __forceinline__ void msmerge(float& m, float& s, float om, float os) {
    float dm = m - om;
    float e  = ex2f(-fabsf(dm));
    s = (dm >= 0.0f) ? fmaf(os, e, s) : fmaf(s, e, os);
    m = fmaxf(m, om);
}
#define CP_ASYNC16(dst, src) \
    asm volatile("cp.async.cg.shared.global [%0], [%1], 16;" :: "r"(dst), "l"(src) : "memory")
#define CP_COMMIT() asm volatile("cp.async.commit_group;" ::: "memory")
#define CP_WAIT1()  asm volatile("cp.async.wait_group 1;" ::: "memory")
#define CP_WAIT0()  asm volatile("cp.async.wait_group 0;" ::: "memory")

static __device__ __forceinline__ void load_tile(uint32_t dstBase, int row0, int tid) {
    const char* hb = (const char*)g_hi + (size_t)row0 * 256;
#pragma unroll
    for (int j = 0; j < 8; j++) {
        int q   = tid + j * THREADS;
        int row = q >> 4;
        int c16 = q & 15;
        uint32_t dst = dstBase + (uint32_t)(row << 8)
                     + (uint32_t)((c16 ^ (row & 7)) << 4);
        CP_ASYNC16(dst, hb + row * 256 + c16 * 16);
    }
}

// ---------------------------------------------------------------------------
__global__ void pack_kernel(const float* __restrict__ fo, const float* __restrict__ fa) {
    int idx4 = blockIdx.x * blockDim.x + threadIdx.x;
    int row  = idx4 >> 5;
    const float* src = (row < BHALF) ? fo : fa;
    int lrow = (row < BHALF) ? row : row - BHALF;
    float4 v = reinterpret_cast<const float4*>(src)[(lrow << 5) + (idx4 & 31)];
    ushort4 h4;
    h4.x = __half_as_ushort(__float2half_rn(v.x));
    h4.y = __half_as_ushort(__float2half_rn(v.y));
    h4.z = __half_as_ushort(__float2half_rn(v.z));
    h4.w = __half_as_ushort(__float2half_rn(v.w));
    reinterpret_cast<ushort4*>(g_hi)[idx4] = h4;
}

// ---------------------------------------------------------------------------
__global__ __launch_bounds__(THREADS, 1) void simclr_mma() {
    extern __shared__ __align__(1024) char dynsm[];
    __shared__ float sm_m[2][128], sm_s[2][128];

    const uint32_t sbase = smem_u32(dynsm);
    const int tid  = threadIdx.x;
    const int wid  = tid >> 5;
    const int lane = tid & 31;
    const int wy   = wid & 3;
    const int wx   = wid >> 2;
    const int bid  = blockIdx.x;
    const int r0   = bid * 128;
    const int dmax = (bid < 64) ? 64 : 63;

    const uint32_t a_row  = (uint32_t)(wy * 32 + (lane & 15));
    const uint32_t a_base = sbase + (a_row << 8);
    const uint32_t a_swz  = (a_row & 7) << 4;
    const uint32_t a_koff = (lane >> 4) << 4;

    const uint32_t b_row  = (uint32_t)(wx * 64 + ((lane >> 4) << 3) + (lane & 7));
    const uint32_t b_base = sbase + B_OFF + (b_row << 8);
    const uint32_t b_swz  = (b_row & 7) << 4;
    const uint32_t b_koff = ((lane >> 3) & 1) << 4;

    load_tile(sbase, r0, tid);           // A stripe, resident all kernel
    load_tile(sbase + B_OFF, r0, tid);   // B tile d=0
    CP_COMMIT();

    const float C2    = 20.609929155556627f;   // (1/0.07)*log2(e)
    const float MASKV = -3.0e28f;

    float m[4], s[4];
#pragma unroll
    for (int i = 0; i < 4; i++) { m[i] = -1e30f; s[i] = 0.0f; }

    float acc0[2][8][4], acc1[2][8][4];

    // ---- issue all MMAs for tile d into acc ----
    auto do_mma = [&](int d, float (&acc)[2][8][4]) {
        const uint32_t bbuf = b_base + ((uint32_t)(d & 1) << 15);
#pragma unroll
        for (int mi = 0; mi < 2; mi++)
#pragma unroll
            for (int nj = 0; nj < 8; nj++)
#pragma unroll
                for (int k = 0; k < 4; k++) acc[mi][nj][k] = 0.0f;
#pragma unroll 4
        for (int kc = 0; kc < 8; kc++) {
            const uint32_t akx = ((uint32_t)(kc << 5) + a_koff) ^ a_swz;
            const uint32_t bkx = ((uint32_t)(kc << 5) + b_koff) ^ b_swz;
            uint32_t ah[2][4];
#pragma unroll
            for (int mi = 0; mi < 2; mi++)
                ldmx4(ah[mi], a_base + (uint32_t)(mi << 12) + akx);
            uint32_t bh[4][4];
#pragma unroll
            for (int p = 0; p < 4; p++)
                ldmx4(bh[p], bbuf + (uint32_t)(p << 12) + bkx);
#pragma unroll
            for (int mi = 0; mi < 2; mi++)
#pragma unroll
                for (int p = 0; p < 4; p++) {
                    mma16816(acc[mi][2 * p],     ah[mi], &bh[p][0]);
                    mma16816(acc[mi][2 * p + 1], ah[mi], &bh[p][2]);
                }
        }
    };

    // ---- epilogue for tile e (runs under the tensor shadow of tile e+1) ----
    auto do_epi = [&](int e, float (&acc)[2][8][4]) {
        const int j = (bid + e) & 127;
        if ((e == 0) | (e == 64)) {
            const bool isdiag = (e == 0);
#pragma unroll
            for (int mi = 0; mi < 2; mi++)
#pragma unroll
                for (int rh = 0; rh < 2; rh++) {
                    const int r_l = wy * 32 + mi * 16 + rh * 8 + (lane >> 2);
#pragma unroll
                    for (int nj = 0; nj < 8; nj++)
#pragma unroll
                        for (int jj = 0; jj < 2; jj++) {
                            float& v = acc[mi][nj][rh * 2 + jj];
                            const int c_l = wx * 64 + nj * 8 + ((lane & 3) << 1) + jj;
                            if (c_l == r_l) {
                                if (isdiag) v = MASKV;
                                else {
                                    g_pos[(bid << 7) + r_l] = v;
                                    g_pos[(j << 7) + r_l]   = v;
                                }
                            }
                        }
                }
        }
        // row-side online LSE with skip guard
#pragma unroll
        for (int mi = 0; mi < 2; mi++)
#pragma unroll
            for (int rh = 0; rh < 2; rh++) {
                const int ri = mi * 2 + rh;
                float mxr = acc[mi][0][rh * 2];
#pragma unroll
                for (int nj = 0; nj < 8; nj++) {
                    mxr = fmaxf(mxr, acc[mi][nj][rh * 2]);
                    mxr = fmaxf(mxr, acc[mi][nj][rh * 2 + 1]);
                }
                const float mx2 = mxr * C2;
                if (mx2 > m[ri] - 30.0f) {
                    const float nm = fmaxf(m[ri], mx2);
                    float a0 = 0.0f;
#pragma unroll
                    for (int nj = 0; nj < 8; nj++) {
                        a0 += ex2f(fmaf(acc[mi][nj][rh * 2],     C2, -nm));
                        a0 += ex2f(fmaf(acc[mi][nj][rh * 2 + 1], C2, -nm));
                    }
                    s[ri] = s[ri] * ex2f(m[ri] - nm) + a0;
                    m[ri] = nm;
                }
            }
        // column-side partials: split max-reduce then sum-reduce (4 ex2/col)
        if (e != 0) {
            const int slotBase = (((j * 65 + e) << 2) + wy) * 128 + wx * 64;
#pragma unroll
            for (int q = 0; q < 16; q++) {
                const int nj = q >> 1, jj = q & 1;
                const float v0 = acc[0][nj][jj],     v1 = acc[0][nj][2 + jj];
                const float v2 = acc[1][nj][jj],     v3 = acc[1][nj][2 + jj];
                float mx = fmaxf(fmaxf(v0, v1), fmaxf(v2, v3));
#pragma unroll
                for (int off = 4; off <= 16; off <<= 1)
                    mx = fmaxf(mx, __shfl_xor_sync(0xffffffffu, mx, off));
                const float nm = mx * C2;
                float sum = ex2f(fmaf(v0, C2, -nm)) + ex2f(fmaf(v1, C2, -nm))
                          + ex2f(fmaf(v2, C2, -nm)) + ex2f(fmaf(v3, C2, -nm));
#pragma unroll
                for (int off = 4; off <= 16; off <<= 1)
                    sum += __shfl_xor_sync(0xffffffffu, sum, off);
                if (lane < 4)
                    g_cp[slotBase + nj * 8 + lane * 2 + jj] = make_float2(nm, sum);
            }
        }
    };

    // ---- pipelined step: sync, prefetch, wait, MMA(i), epi(i-1) ----
    auto step = [&](int i, float (&accC)[2][8][4], float (&accP)[2][8][4]) {
        __syncthreads();   // all warps done with LDSM of tile i-1 (buffer (i+1)&1)
        if (i < dmax) {
            load_tile(sbase + B_OFF + (uint32_t)(((i + 1) & 1) << 15),
                      ((bid + i + 1) & 127) << 7, tid);
            CP_COMMIT();
            CP_WAIT1();
        } else {
            CP_WAIT0();
        }
        do_mma(i, accC);
        if (i > 0) do_epi(i - 1, accP);
    };

    for (int d = 0; d < 63; d += 2) {
        step(d,     acc0, acc1);
        step(d + 1, acc1, acc0);
    }
    if (dmax == 64) {
        step(64, acc0, acc1);   // includes epi(63, acc1)
        do_epi(64, acc0);
    } else {
        do_epi(63, acc1);
    }

    // ---- merge row state across the 4 lanes sharing each row, write g_rp ----
#pragma unroll
    for (int off = 1; off <= 2; off <<= 1)
#pragma unroll
        for (int ri = 0; ri < 4; ri++) {
            const float om = __shfl_xor_sync(0xffffffffu, m[ri], off);
            const float os = __shfl_xor_sync(0xffffffffu, s[ri], off);
            msmerge(m[ri], s[ri], om, os);
        }
    if ((lane & 3) == 0) {
#pragma unroll
        for (int mi = 0; mi < 2; mi++)
#pragma unroll
            for (int rh = 0; rh < 2; rh++) {
                const int r_l = wy * 32 + mi * 16 + rh * 8 + (lane >> 2);
                sm_m[wx][r_l] = m[mi * 2 + rh];
                sm_s[wx][r_l] = s[mi * 2 + rh];
            }
    }
    __syncthreads();
    if (tid < 128) {
        float mm = sm_m[0][tid], ss = sm_s[0][tid];
        msmerge(mm, ss, sm_m[1][tid], sm_s[1][tid]);
        g_rp[(bid << 7) + tid] = make_float2(mm, ss);
    }
}

// ---------------------------------------------------------------------------
__global__ __launch_bounds__(128) void simclr_merge() {
    __shared__ float red[4];
    const int r   = blockIdx.x;
    const int k   = threadIdx.x;
    const int dmx = (r >= 64) ? 64 : 63;

    float mm[4], ss[4];
    {
        const float2 p0 = g_cp[(((r * 65 + 1) << 2) + 0) * 128 + k];
        const float2 p1 = g_cp[(((r * 65 + 1) << 2) + 1) * 128 + k];
        const float2 p2 = g_cp[(((r * 65 + 1) << 2) + 2) * 128 + k];
        const float2 p3 = g_cp[(((r * 65 + 1) << 2) + 3) * 128 + k];
        mm[0] = p0.x; ss[0] = p0.y;  mm[1] = p1.x; ss[1] = p1.y;
        mm[2] = p2.x; ss[2] = p2.y;  mm[3] = p3.x; ss[3] = p3.y;
    }
    for (int d = 2; d <= dmx; d++) {
#pragma unroll
        for (int w = 0; w < 4; w++) {
            const float2 p = g_cp[(((r * 65 + d) << 2) + w) * 128 + k];
            msmerge(mm[w], ss[w], p.x, p.y);
        }
    }
    msmerge(mm[0], ss[0], mm[1], ss[1]);
    msmerge(mm[2], ss[2], mm[3], ss[3]);
    msmerge(mm[0], ss[0], mm[2], ss[2]);
    const float2 rp = g_rp[(r << 7) + k];
    msmerge(mm[0], ss[0], rp.x, rp.y);

    const float LN2   = 0.6931471805599453f;
    const float INV_T = 14.285714285714286f;
    const float lse   = (mm[0] + log2f(ss[0])) * LN2;
    float term = lse - g_pos[(r << 7) + k] * INV_T;
#pragma unroll
    for (int off = 16; off; off >>= 1)
        term += __shfl_xor_sync(0xffffffffu, term, off);
    if ((k & 31) == 0) red[k >> 5] = term;
    __syncthreads();
    if (k == 0) g_partials[r] = red[0] + red[1] + red[2] + red[3];
}

__global__ void simclr_final(float* __restrict__ out) {
    __shared__ float red[NBLK];
    red[threadIdx.x] = g_partials[threadIdx.x];
    __syncthreads();
    for (int off = NBLK / 2; off; off >>= 1) {
        if (threadIdx.x < off) red[threadIdx.x] += red[threadIdx.x + off];
        __syncthreads();
    }
    if (threadIdx.x == 0) out[0] = red[0] * (1.0f / (float)NTOT);
}

extern "C" void kernel_launch(void* const* d_in, const int* in_sizes, int n_in,
                              void* d_out, int out_size) {
    const float* fo = (const float*)d_in[0];
    const float* fa = (const float*)d_in[1];
    float* out = (float*)d_out;

    cudaFuncSetAttribute(simclr_mma, cudaFuncAttributeMaxDynamicSharedMemorySize, SMEM_DYN);

    pack_kernel<<<NTOT * 128 / 4 / THREADS, THREADS>>>(fo, fa);
    simclr_mma<<<NBLK, THREADS, SMEM_DYN>>>();
    simclr_merge<<<NBLK, 128>>>();
    simclr_final<<<1, NBLK>>>(out);
}

// round 8
// speedup vs baseline: 27.3248x; 1.0997x over previous
#include <cuda_runtime.h>
#include <cuda_fp16.h>
#include <math.h>
#include <stdint.h>

// ===========================================================================
// SimCLR loss, symmetry-halved HMMA GEMM + two-sided online logsumexp.
// Epilogue of tile d-1 is interleaved INTO tile d's MMA k-loop (one column
// chunk + one row chunk per kc) so MUFU/shfl/fma run under the tensor shadow.
// Column-side cross-lane reductions are f16x2-packed: 3 shfl+max.f16x2 and
// 3 shfl+add.f16x2 per column PAIR (48 shfl/thread/tile, was 96).
// Pure fp16 single-term D = Ahi*Bhi^T (measured loss rel_err ~1e-6).
// Baseline ISA only (compute_103: no tcgen05/TMA).
// ===========================================================================

#define BHALF   8192
#define NTOT    16384
#define NBLK    128
#define THREADS 256

#define B_OFF   32768
#define SMEM_DYN (B_OFF + 2 * 32768)     // 98304

__device__ __align__(16) __half g_hi[NTOT * 128];
__device__ uint2  g_cph[128 * 65 * 4 * 64];   // [j][d][wy][colpair] (m.h2, s.h2)
__device__ float2 g_rp[NTOT];
__device__ float  g_pos[NTOT];
__device__ float  g_partials[NBLK];

// ---------------------------------------------------------------------------
static __device__ __forceinline__ uint32_t smem_u32(const void* p) {
    uint32_t a;
    asm("{ .reg .u64 t; cvta.to.shared.u64 t, %1; cvt.u32.u64 %0, t; }"
        : "=r"(a) : "l"(p));
    return a;
}
static __device__ __forceinline__ float ex2f(float x) {
    float r; asm("ex2.approx.ftz.f32 %0, %1;" : "=f"(r) : "f"(x)); return r;
}
static __device__ __forceinline__ void ldmx4(uint32_t* r, uint32_t addr) {
    asm volatile("ldmatrix.sync.aligned.m8n8.x4.shared.b16 {%0,%1,%2,%3}, [%4];"
                 : "=r"(r[0]), "=r"(r[1]), "=r"(r[2]), "=r"(r[3]) : "r"(addr));
}
static __device__ __forceinline__ void mma16816(float* c, const uint32_t* a,
                                                const uint32_t* b) {
    asm volatile(
        "mma.sync.aligned.m16n8k16.row.col.f32.f16.f16.f32 "
        "{%0,%1,%2,%3}, {%4,%5,%6,%7}, {%8,%9}, {%0,%1,%2,%3};"
        : "+f"(c[0]), "+f"(c[1]), "+f"(c[2]), "+f"(c[3])
        : "r"(a[0]), "r"(a[1]), "r"(a[2]), "r"(a[3]), "r"(b[0]), "r"(b[1]));
}
static __device__ __forceinline__ void msmerge(float& m, float& s, float om, float os) {
    float dm = m - om;
    float e  = ex2f(-fabsf(dm));
    s = (dm >= 0.0f) ? fmaf(os, e, s) : fmaf(s, e, os);
    m = fmaxf(m, om);
}
// f16x2 helpers (lo = first arg)
static __device__ __forceinline__ uint32_t pack_h2(float lo, float hi) {
    uint32_t r; asm("cvt.rn.f16x2.f32 %0, %1, %2;" : "=r"(r) : "f"(hi), "f"(lo)); return r;
}
static __device__ __forceinline__ uint32_t hmax2u(uint32_t a, uint32_t b) {
    uint32_t r; asm("max.f16x2 %0, %1, %2;" : "=r"(r) : "r"(a), "r"(b)); return r;
}
static __device__ __forceinline__ uint32_t hadd2u(uint32_t a, uint32_t b) {
    uint32_t r; asm("add.rn.f16x2 %0, %1, %2;" : "=r"(r) : "r"(a), "r"(b)); return r;
}
static __device__ __forceinline__ float h2_lo(uint32_t u) {
    float f; asm("{ .reg .b16 l,h; mov.b32 {l,h}, %1; cvt.f32.f16 %0, l; }"
                 : "=f"(f) : "r"(u)); return f;
}
static __device__ __forceinline__ float h2_hi(uint32_t u) {
    float f; asm("{ .reg .b16 l,h; mov.b32 {l,h}, %1; cvt.f32.f16 %0, h; }"
                 : "=f"(f) : "r"(u)); return f;
}
#define CP_ASYNC16(dst, src) \
    asm volatile("cp.async.cg.shared.global [%0], [%1], 16;" :: "r"(dst), "l"(src) : "memory")
#define CP_COMMIT() asm volatile("cp.async.commit_group;" ::: "memory")
#define CP_WAIT1()  asm volatile("cp.async.wait_group 1;" ::: "memory")
#define CP_WAIT0()  asm volatile("cp.async.wait_group 0;" ::: "memory")

static __device__ __forceinline__ void load_tile(uint32_t dstBase, int row0, int tid) {
    const char* hb = (const char*)g_hi + (size_t)row0 * 256;
#pragma unroll
    for (int j = 0; j < 8; j++) {
        int q   = tid + j * THREADS;
        int row = q >> 4;
        int c16 = q & 15;
        uint32_t dst = dstBase + (uint32_t)(row << 8)
                     + (uint32_t)((c16 ^ (row & 7)) << 4);
        CP_ASYNC16(dst, hb + row * 256 + c16 * 16);
    }
}

// ---------------------------------------------------------------------------
__global__ void pack_kernel(const float* __restrict__ fo, const float* __restrict__ fa) {
    int idx4 = blockIdx.x * blockDim.x + threadIdx.x;
    int row  = idx4 >> 5;
    const float* src = (row < BHALF) ? fo : fa;
    int lrow = (row < BHALF) ? row : row - BHALF;
    float4 v = reinterpret_cast<const float4*>(src)[(lrow << 5) + (idx4 & 31)];
    ushort4 h4;
    h4.x = __half_as_ushort(__float2half_rn(v.x));
    h4.y = __half_as_ushort(__float2half_rn(v.y));
    h4.z = __half_as_ushort(__float2half_rn(v.z));
    h4.w = __half_as_ushort(__float2half_rn(v.w));
    reinterpret_cast<ushort4*>(g_hi)[idx4] = h4;
}

// ---------------------------------------------------------------------------
__global__ __launch_bounds__(THREADS, 1) void simclr_mma() {
    extern __shared__ __align__(1024) char dynsm[];
    __shared__ float sm_m[2][128], sm_s[2][128];

    const uint32_t sbase = smem_u32(dynsm);
    const int tid  = threadIdx.x;
    const int wid  = tid >> 5;
    const int lane = tid & 31;
    const int wy   = wid & 3;
    const int wx   = wid >> 2;
    const int bid  = blockIdx.x;
    const int r0   = bid * 128;
    const int dmax = (bid < 64) ? 64 : 63;

    const uint32_t a_row  = (uint32_t)(wy * 32 + (lane & 15));
    const uint32_t a_base = sbase + (a_row << 8);
    const uint32_t a_swz  = (a_row & 7) << 4;
    const uint32_t a_koff = (lane >> 4) << 4;

    const uint32_t b_row  = (uint32_t)(wx * 64 + ((lane >> 4) << 3) + (lane & 7));
    const uint32_t b_base = sbase + B_OFF + (b_row << 8);
    const uint32_t b_swz  = (b_row & 7) << 4;
    const uint32_t b_koff = ((lane >> 3) & 1) << 4;

    load_tile(sbase, r0, tid);           // A stripe, resident
    load_tile(sbase + B_OFF, r0, tid);   // B tile d=0
    CP_COMMIT();

    const float C2    = 20.609929155556627f;   // (1/0.07)*log2(e)
    const float MASKV = -3.0e28f;

    float m[4], s[4];
#pragma unroll
    for (int i = 0; i < 4; i++) { m[i] = -1e30f; s[i] = 0.0f; }

    float acc0[2][8][4], acc1[2][8][4];

    // --- column chunk: one nj (two adjacent columns per lane group), f16x2 ---
    auto col_chunk = [&](int nj, const float (&acc)[2][8][4], int slotRow) {
        const float v00 = acc[0][nj][0], v01 = acc[0][nj][2];
        const float v02 = acc[1][nj][0], v03 = acc[1][nj][2];
        const float v10 = acc[0][nj][1], v11 = acc[0][nj][3];
        const float v12 = acc[1][nj][1], v13 = acc[1][nj][3];
        const float mx0 = fmaxf(fmaxf(v00, v01), fmaxf(v02, v03)) * C2;
        const float mx1 = fmaxf(fmaxf(v10, v11), fmaxf(v12, v13)) * C2;
        uint32_t m2 = pack_h2(mx0, mx1);
        m2 = hmax2u(m2, __shfl_xor_sync(0xffffffffu, m2, 4));
        m2 = hmax2u(m2, __shfl_xor_sync(0xffffffffu, m2, 8));
        m2 = hmax2u(m2, __shfl_xor_sync(0xffffffffu, m2, 16));
        const float m0 = h2_lo(m2), m1 = h2_hi(m2);
        float s0 = ex2f(fmaf(v00, C2, -m0)) + ex2f(fmaf(v01, C2, -m0))
                 + ex2f(fmaf(v02, C2, -m0)) + ex2f(fmaf(v03, C2, -m0));
        float s1 = ex2f(fmaf(v10, C2, -m1)) + ex2f(fmaf(v11, C2, -m1))
                 + ex2f(fmaf(v12, C2, -m1)) + ex2f(fmaf(v13, C2, -m1));
        uint32_t s2 = pack_h2(s0, s1);
        s2 = hadd2u(s2, __shfl_xor_sync(0xffffffffu, s2, 4));
        s2 = hadd2u(s2, __shfl_xor_sync(0xffffffffu, s2, 8));
        s2 = hadd2u(s2, __shfl_xor_sync(0xffffffffu, s2, 16));
        if (lane < 4)
            g_cph[slotRow + wx * 32 + nj * 4 + lane] = make_uint2(m2, s2);
    };

    // --- row chunk: guarded online LSE update for one ri ---
    auto row_chunk = [&](int ri, const float (&acc)[2][8][4]) {
        const int mi = ri >> 1, rh = ri & 1;
        float mxr = acc[mi][0][rh * 2];
#pragma unroll
        for (int nj = 0; nj < 8; nj++) {
            mxr = fmaxf(mxr, acc[mi][nj][rh * 2]);
            mxr = fmaxf(mxr, acc[mi][nj][rh * 2 + 1]);
        }
        const float mx2 = mxr * C2;
        if (mx2 > m[ri] - 30.0f) {
            const float nm = fmaxf(m[ri], mx2);
            float a0 = 0.0f;
#pragma unroll
            for (int nj = 0; nj < 8; nj++) {
                a0 += ex2f(fmaf(acc[mi][nj][rh * 2],     C2, -nm));
                a0 += ex2f(fmaf(acc[mi][nj][rh * 2 + 1], C2, -nm));
            }
            s[ri] = s[ri] * ex2f(m[ri] - nm) + a0;
            m[ri] = nm;
        }
    };

    // --- plain MMA (no interleaved epi), for tiles 0 and 1 ---
    auto do_mma = [&](int d, float (&acc)[2][8][4]) {
        const uint32_t bbuf = b_base + ((uint32_t)(d & 1) << 15);
#pragma unroll
        for (int mi = 0; mi < 2; mi++)
#pragma unroll
            for (int nj = 0; nj < 8; nj++)
#pragma unroll
                for (int k = 0; k < 4; k++) acc[mi][nj][k] = 0.0f;
#pragma unroll
        for (int kc = 0; kc < 8; kc++) {
            const uint32_t akx = ((uint32_t)(kc << 5) + a_koff) ^ a_swz;
            const uint32_t bkx = ((uint32_t)(kc << 5) + b_koff) ^ b_swz;
            uint32_t ah[2][4], bh[4][4];
#pragma unroll
            for (int mi = 0; mi < 2; mi++)
                ldmx4(ah[mi], a_base + (uint32_t)(mi << 12) + akx);
#pragma unroll
            for (int p = 0; p < 4; p++)
                ldmx4(bh[p], bbuf + (uint32_t)(p << 12) + bkx);
#pragma unroll
            for (int mi = 0; mi < 2; mi++)
#pragma unroll
                for (int p = 0; p < 4; p++) {
                    mma16816(acc[mi][2 * p],     ah[mi], &bh[p][0]);
                    mma16816(acc[mi][2 * p + 1], ah[mi], &bh[p][2]);
                }
        }
    };

    // --- full epilogue for special tiles e in {0, 64} and the tail ---
    auto do_epi_full = [&](int e, float (&acc)[2][8][4]) {
        const int j = (bid + e) & 127;
        if ((e == 0) | (e == 64)) {
            const bool isdiag = (e == 0);
#pragma unroll
            for (int mi = 0; mi < 2; mi++)
#pragma unroll
                for (int rh = 0; rh < 2; rh++) {
                    const int r_l = wy * 32 + mi * 16 + rh * 8 + (lane >> 2);
#pragma unroll
                    for (int nj = 0; nj < 8; nj++)
#pragma unroll
                        for (int jj = 0; jj < 2; jj++) {
                            float& v = acc[mi][nj][rh * 2 + jj];
                            const int c_l = wx * 64 + nj * 8 + ((lane & 3) << 1) + jj;
                            if (c_l == r_l) {
                                if (isdiag) v = MASKV;
                                else {
                                    g_pos[(bid << 7) + r_l] = v;
                                    g_pos[(j << 7) + r_l]   = v;
                                }
                            }
                        }
                }
        }
#pragma unroll
        for (int ri = 0; ri < 4; ri++) row_chunk(ri, acc);
        if (e != 0) {
            const int slotRow = (((j * 65 + e) << 2) + wy) * 64;
#pragma unroll
            for (int nj = 0; nj < 8; nj++) col_chunk(nj, acc, slotRow);
        }
    };

    // --- interleaved: MMAs of tile i + epilogue chunks of tile i-1 ---
    auto do_tile = [&](int i, float (&accC)[2][8][4], float (&accP)[2][8][4]) {
        const uint32_t bbuf = b_base + ((uint32_t)(i & 1) << 15);
        const int e = i - 1;
        const int j = (bid + e) & 127;
        const int slotRow = (((j * 65 + e) << 2) + wy) * 64;
#pragma unroll
        for (int mi = 0; mi < 2; mi++)
#pragma unroll
            for (int nj = 0; nj < 8; nj++)
#pragma unroll
                for (int k = 0; k < 4; k++) accC[mi][nj][k] = 0.0f;
#pragma unroll
        for (int kc = 0; kc < 8; kc++) {
            const uint32_t akx = ((uint32_t)(kc << 5) + a_koff) ^ a_swz;
            const uint32_t bkx = ((uint32_t)(kc << 5) + b_koff) ^ b_swz;
            uint32_t ah[2][4], bh[4][4];
#pragma unroll
            for (int mi = 0; mi < 2; mi++)
                ldmx4(ah[mi], a_base + (uint32_t)(mi << 12) + akx);
#pragma unroll
            for (int p = 0; p < 4; p++)
                ldmx4(bh[p], bbuf + (uint32_t)(p << 12) + bkx);
#pragma unroll
            for (int mi = 0; mi < 2; mi++)
#pragma unroll
                for (int p = 0; p < 4; p++) {
                    mma16816(accC[mi][2 * p],     ah[mi], &bh[p][0]);
                    mma16816(accC[mi][2 * p + 1], ah[mi], &bh[p][2]);
                }
            col_chunk(kc, accP, slotRow);      // epilogue under tensor shadow
            if (kc >= 4) row_chunk(kc - 4, accP);
        }
    };

    // --- prefetch/visibility handshake: sync(buffer) -> prefetch -> wait -> sync(vis)
    auto handshake = [&](int i) {
        __syncthreads();                       // buffer (i+1)&1 free of readers
        if (i < dmax) {
            load_tile(sbase + B_OFF + (uint32_t)(((i + 1) & 1) << 15),
                      ((bid + i + 1) & 127) << 7, tid);
            CP_COMMIT();
            CP_WAIT1();
        } else {
            CP_WAIT0();
        }
        __syncthreads();                       // tile i visible to all warps
    };

    handshake(0); do_mma(0, acc0);
    handshake(1); do_mma(1, acc1); do_epi_full(0, acc0);
    for (int d = 2; d + 1 <= dmax; d += 2) {
        handshake(d);     do_tile(d,     acc0, acc1);
        handshake(d + 1); do_tile(d + 1, acc1, acc0);
    }
    if (dmax == 64) {
        handshake(64); do_tile(64, acc0, acc1);
        do_epi_full(64, acc0);
    } else {
        do_epi_full(63, acc1);
    }

    // --- merge row state across the 4 lanes sharing each row, write g_rp ----
#pragma unroll
    for (int off = 1; off <= 2; off <<= 1)
#pragma unroll
        for (int ri = 0; ri < 4; ri++) {
            const float om = __shfl_xor_sync(0xffffffffu, m[ri], off);
            const float os = __shfl_xor_sync(0xffffffffu, s[ri], off);
            msmerge(m[ri], s[ri], om, os);
        }
    if ((lane & 3) == 0) {
#pragma unroll
        for (int mi = 0; mi < 2; mi++)
#pragma unroll
            for (int rh = 0; rh < 2; rh++) {
                const int r_l = wy * 32 + mi * 16 + rh * 8 + (lane >> 2);
                sm_m[wx][r_l] = m[mi * 2 + rh];
                sm_s[wx][r_l] = s[mi * 2 + rh];
            }
    }
    __syncthreads();
    if (tid < 128) {
        float mm = sm_m[0][tid], ss = sm_s[0][tid];
        msmerge(mm, ss, sm_m[1][tid], sm_s[1][tid]);
        g_rp[(bid << 7) + tid] = make_float2(mm, ss);
    }
}

// ---------------------------------------------------------------------------
__global__ __launch_bounds__(128) void simclr_merge() {
    __shared__ float red[4];
    const int r   = blockIdx.x;
    const int k   = threadIdx.x;
    const int dmx = (r >= 64) ? 64 : 63;
    const int pr  = k >> 1;              // column pair index
    const int hi  = k & 1;

    float mm[4], ss[4];
#pragma unroll
    for (int w = 0; w < 4; w++) {
        const uint2 p = g_cph[(((r * 65 + 1) << 2) + w) * 64 + pr];
        mm[w] = hi ? h2_hi(p.x) : h2_lo(p.x);
        ss[w] = hi ? h2_hi(p.y) : h2_lo(p.y);
    }
    for (int d = 2; d <= dmx; d++) {
#pragma unroll
        for (int w = 0; w < 4; w++) {
            const uint2 p = g_cph[(((r * 65 + d) << 2) + w) * 64 + pr];
            const float pm = hi ? h2_hi(p.x) : h2_lo(p.x);
            const float ps = hi ? h2_hi(p.y) : h2_lo(p.y);
            msmerge(mm[w], ss[w], pm, ps);
        }
    }
    msmerge(mm[0], ss[0], mm[1], ss[1]);
    msmerge(mm[2], ss[2], mm[3], ss[3]);
    msmerge(mm[0], ss[0], mm[2], ss[2]);
    const float2 rp = g_rp[(r << 7) + k];
    msmerge(mm[0], ss[0], rp.x, rp.y);

    const float LN2   = 0.6931471805599453f;
    const float INV_T = 14.285714285714286f;
    const float lse   = (mm[0] + log2f(ss[0])) * LN2;
    float term = lse - g_pos[(r << 7) + k] * INV_T;
#pragma unroll
    for (int off = 16; off; off >>= 1)
        term += __shfl_xor_sync(0xffffffffu, term, off);
    if ((k & 31) == 0) red[k >> 5] = term;
    __syncthreads();
    if (k == 0) g_partials[r] = red[0] + red[1] + red[2] + red[3];
}

__global__ void simclr_final(float* __restrict__ out) {
    __shared__ float red[NBLK];
    red[threadIdx.x] = g_partials[threadIdx.x];
    __syncthreads();
    for (int off = NBLK / 2; off; off >>= 1) {
        if (threadIdx.x < off) red[threadIdx.x] += red[threadIdx.x + off];
        __syncthreads();
    }
    if (threadIdx.x == 0) out[0] = red[0] * (1.0f / (float)NTOT);
}

extern "C" void kernel_launch(void* const* d_in, const int* in_sizes, int n_in,
                              void* d_out, int out_size) {
    const float* fo = (const float*)d_in[0];
    const float* fa = (const float*)d_in[1];
    float* out = (float*)d_out;

    cudaFuncSetAttribute(simclr_mma, cudaFuncAttributeMaxDynamicSharedMemorySize, SMEM_DYN);

    pack_kernel<<<NTOT * 128 / 4 / THREADS, THREADS>>>(fo, fa);
    simclr_mma<<<NBLK, THREADS, SMEM_DYN>>>();
    simclr_merge<<<NBLK, 128>>>();
    simclr_final<<<1, NBLK>>>(out);
}

// round 9
// speedup vs baseline: 28.0736x; 1.0274x over previous
#include <cuda_runtime.h>
#include <cuda_fp16.h>
#include <math.h>
#include <stdint.h>

// ===========================================================================
// SimCLR loss, symmetry-halved HMMA GEMM + two-sided online logsumexp.
// 512 threads / 16 warps per CTA, 4x4 warp grid (32x32 warp tiles): 4 warps
// per SMSP to hide LDSM/SHFL/MUFU latency under the tensor pipe. Epilogue of
// tile d-1 interleaved into tile d's MMA k-loop. f16x2-packed column
// reductions. Pure fp16 single-term D = Ahi*Bhi^T (loss rel_err ~8e-7).
// Baseline ISA only (compute_103: no tcgen05/TMA).
// ===========================================================================

#define BHALF   8192
#define NTOT    16384
#define NBLK    128
#define THREADS 512

#define B_OFF   32768
#define SMEM_DYN (B_OFF + 2 * 32768)     // 98304

__device__ __align__(16) __half g_hi[NTOT * 128];
__device__ uint2  g_cph[128 * 65 * 4 * 64];   // [j][d][wy][colpair] (m.h2, s.h2)
__device__ float2 g_rp[NTOT];
__device__ float  g_pos[NTOT];
__device__ float  g_partials[NBLK];

// ---------------------------------------------------------------------------
static __device__ __forceinline__ uint32_t smem_u32(const void* p) {
    uint32_t a;
    asm("{ .reg .u64 t; cvta.to.shared.u64 t, %1; cvt.u32.u64 %0, t; }"
        : "=r"(a) : "l"(p));
    return a;
}
static __device__ __forceinline__ float ex2f(float x) {
    float r; asm("ex2.approx.ftz.f32 %0, %1;" : "=f"(r) : "f"(x)); return r;
}
static __device__ __forceinline__ void ldmx4(uint32_t* r, uint32_t addr) {
    asm volatile("ldmatrix.sync.aligned.m8n8.x4.shared.b16 {%0,%1,%2,%3}, [%4];"
                 : "=r"(r[0]), "=r"(r[1]), "=r"(r[2]), "=r"(r[3]) : "r"(addr));
}
static __device__ __forceinline__ void mma16816(float* c, const uint32_t* a,
                                                const uint32_t* b) {
    asm volatile(
        "mma.sync.aligned.m16n8k16.row.col.f32.f16.f16.f32 "
        "{%0,%1,%2,%3}, {%4,%5,%6,%7}, {%8,%9}, {%0,%1,%2,%3};"
        : "+f"(c[0]), "+f"(c[1]), "+f"(c[2]), "+f"(c[3])
        : "r"(a[0]), "r"(a[1]), "r"(a[2]), "r"(a[3]), "r"(b[0]), "r"(b[1]));
}
static __device__ __forceinline__ void msmerge(float& m, float& s, float om, float os) {
    float dm = m - om;
    float e  = ex2f(-fabsf(dm));
    s = (dm >= 0.0f) ? fmaf(os, e, s) : fmaf(s, e, os);
    m = fmaxf(m, om);
}
static __device__ __forceinline__ uint32_t pack_h2(float lo, float hi) {
    uint32_t r; asm("cvt.rn.f16x2.f32 %0, %1, %2;" : "=r"(r) : "f"(hi), "f"(lo)); return r;
}
static __device__ __forceinline__ uint32_t hmax2u(uint32_t a, uint32_t b) {
    uint32_t r; asm("max.f16x2 %0, %1, %2;" : "=r"(r) : "r"(a), "r"(b)); return r;
}
static __device__ __forceinline__ uint32_t hadd2u(uint32_t a, uint32_t b) {
    uint32_t r; asm("add.rn.f16x2 %0, %1, %2;" : "=r"(r) : "r"(a), "r"(b)); return r;
}
static __device__ __forceinline__ float h2_lo(uint32_t u) {
    float f; asm("{ .reg .b16 l,h; mov.b32 {l,h}, %1; cvt.f32.f16 %0, l; }"
                 : "=f"(f) : "r"(u)); return f;
}
static __device__ __forceinline__ float h2_hi(uint32_t u) {
    float f; asm("{ .reg .b16 l,h; mov.b32 {l,h}, %1; cvt.f32.f16 %0, h; }"
                 : "=f"(f) : "r"(u)); return f;
}
#define CP_ASYNC16(dst, src) \
    asm volatile("cp.async.cg.shared.global [%0], [%1], 16;" :: "r"(dst), "l"(src) : "memory")
#define CP_COMMIT() asm volatile("cp.async.commit_group;" ::: "memory")
#define CP_WAIT1()  asm volatile("cp.async.wait_group 1;" ::: "memory")
#define CP_WAIT0()  asm volatile("cp.async.wait_group 0;" ::: "memory")

static __device__ __forceinline__ void load_tile(uint32_t dstBase, int row0, int tid) {
    const char* hb = (const char*)g_hi + (size_t)row0 * 256;
#pragma unroll
    for (int j = 0; j < 4; j++) {
        int q   = tid + j * THREADS;          // 0..2047
        int row = q >> 4;
        int c16 = q & 15;
        uint32_t dst = dstBase + (uint32_t)(row << 8)
                     + (uint32_t)((c16 ^ (row & 7)) << 4);
        CP_ASYNC16(dst, hb + row * 256 + c16 * 16);
    }
}

// ---------------------------------------------------------------------------
__global__ void pack_kernel(const float* __restrict__ fo, const float* __restrict__ fa) {
    int idx4 = blockIdx.x * blockDim.x + threadIdx.x;
    int row  = idx4 >> 5;
    const float* src = (row < BHALF) ? fo : fa;
    int lrow = (row < BHALF) ? row : row - BHALF;
    float4 v = reinterpret_cast<const float4*>(src)[(lrow << 5) + (idx4 & 31)];
    ushort4 h4;
    h4.x = __half_as_ushort(__float2half_rn(v.x));
    h4.y = __half_as_ushort(__float2half_rn(v.y));
    h4.z = __half_as_ushort(__float2half_rn(v.z));
    h4.w = __half_as_ushort(__float2half_rn(v.w));
    reinterpret_cast<ushort4*>(g_hi)[idx4] = h4;
}

// ---------------------------------------------------------------------------
__global__ __launch_bounds__(THREADS, 1) void simclr_mma() {
    extern __shared__ __align__(1024) char dynsm[];
    __shared__ float sm_m[4][128], sm_s[4][128];

    const uint32_t sbase = smem_u32(dynsm);
    const int tid  = threadIdx.x;
    const int wid  = tid >> 5;
    const int lane = tid & 31;
    const int wy   = wid & 3;    // M group (32 rows)
    const int wx   = wid >> 2;   // N group (32 cols)
    const int bid  = blockIdx.x;
    const int r0   = bid * 128;
    const int dmax = (bid < 64) ? 64 : 63;

    const uint32_t a_row  = (uint32_t)(wy * 32 + (lane & 15));
    const uint32_t a_base = sbase + (a_row << 8);
    const uint32_t a_swz  = (a_row & 7) << 4;
    const uint32_t a_koff = (lane >> 4) << 4;

    const uint32_t b_row  = (uint32_t)(wx * 32 + ((lane >> 4) << 3) + (lane & 7));
    const uint32_t b_base = sbase + B_OFF + (b_row << 8);
    const uint32_t b_swz  = (b_row & 7) << 4;
    const uint32_t b_koff = ((lane >> 3) & 1) << 4;

    load_tile(sbase, r0, tid);           // A stripe, resident
    load_tile(sbase + B_OFF, r0, tid);   // B tile d=0
    CP_COMMIT();

    const float C2    = 20.609929155556627f;   // (1/0.07)*log2(e)
    const float MASKV = -3.0e28f;

    float m[4], s[4];
#pragma unroll
    for (int i = 0; i < 4; i++) { m[i] = -1e30f; s[i] = 0.0f; }

    float acc0[2][4][4], acc1[2][4][4];

    // --- column chunk: one nj (8 cols = 4 pairs), f16x2 cross-lane reduce ---
    auto col_chunk = [&](int nj, const float (&acc)[2][4][4], int slotRow) {
        const float v00 = acc[0][nj][0], v01 = acc[0][nj][2];
        const float v02 = acc[1][nj][0], v03 = acc[1][nj][2];
        const float v10 = acc[0][nj][1], v11 = acc[0][nj][3];
        const float v12 = acc[1][nj][1], v13 = acc[1][nj][3];
        const float mx0 = fmaxf(fmaxf(v00, v01), fmaxf(v02, v03)) * C2;
        const float mx1 = fmaxf(fmaxf(v10, v11), fmaxf(v12, v13)) * C2;
        uint32_t m2 = pack_h2(mx0, mx1);
        m2 = hmax2u(m2, __shfl_xor_sync(0xffffffffu, m2, 4));
        m2 = hmax2u(m2, __shfl_xor_sync(0xffffffffu, m2, 8));
        m2 = hmax2u(m2, __shfl_xor_sync(0xffffffffu, m2, 16));
        const float m0 = h2_lo(m2), m1 = h2_hi(m2);
        float s0 = ex2f(fmaf(v00, C2, -m0)) + ex2f(fmaf(v01, C2, -m0))
                 + ex2f(fmaf(v02, C2, -m0)) + ex2f(fmaf(v03, C2, -m0));
        float s1 = ex2f(fmaf(v10, C2, -m1)) + ex2f(fmaf(v11, C2, -m1))
                 + ex2f(fmaf(v12, C2, -m1)) + ex2f(fmaf(v13, C2, -m1));
        uint32_t s2 = pack_h2(s0, s1);
        s2 = hadd2u(s2, __shfl_xor_sync(0xffffffffu, s2, 4));
        s2 = hadd2u(s2, __shfl_xor_sync(0xffffffffu, s2, 8));
        s2 = hadd2u(s2, __shfl_xor_sync(0xffffffffu, s2, 16));
        if (lane < 4)
            g_cph[slotRow + wx * 16 + nj * 4 + lane] = make_uint2(m2, s2);
    };

    // --- row chunk: guarded online LSE update for one ri ---
    auto row_chunk = [&](int ri, const float (&acc)[2][4][4]) {
        const int mi = ri >> 1, rh = ri & 1;
        float mxr = acc[mi][0][rh * 2];
#pragma unroll
        for (int nj = 0; nj < 4; nj++) {
            mxr = fmaxf(mxr, acc[mi][nj][rh * 2]);
            mxr = fmaxf(mxr, acc[mi][nj][rh * 2 + 1]);
        }
        const float mx2 = mxr * C2;
        if (mx2 > m[ri] - 30.0f) {
            const float nm = fmaxf(m[ri], mx2);
            float a0 = 0.0f;
#pragma unroll
            for (int nj = 0; nj < 4; nj++) {
                a0 += ex2f(fmaf(acc[mi][nj][rh * 2],     C2, -nm));
                a0 += ex2f(fmaf(acc[mi][nj][rh * 2 + 1], C2, -nm));
            }
            s[ri] = s[ri] * ex2f(m[ri] - nm) + a0;
            m[ri] = nm;
        }
    };

    // --- plain MMA (no interleaved epi), tiles 0 and 1 ---
    auto do_mma = [&](int d, float (&acc)[2][4][4]) {
        const uint32_t bbuf = b_base + ((uint32_t)(d & 1) << 15);
#pragma unroll
        for (int mi = 0; mi < 2; mi++)
#pragma unroll
            for (int nj = 0; nj < 4; nj++)
#pragma unroll
                for (int k = 0; k < 4; k++) acc[mi][nj][k] = 0.0f;
#pragma unroll
        for (int kc = 0; kc < 8; kc++) {
            const uint32_t akx = ((uint32_t)(kc << 5) + a_koff) ^ a_swz;
            const uint32_t bkx = ((uint32_t)(kc << 5) + b_koff) ^ b_swz;
            uint32_t ah[2][4], bh[2][4];
#pragma unroll
            for (int mi = 0; mi < 2; mi++)
                ldmx4(ah[mi], a_base + (uint32_t)(mi << 12) + akx);
#pragma unroll
            for (int p = 0; p < 2; p++)
                ldmx4(bh[p], bbuf + (uint32_t)(p << 12) + bkx);
#pragma unroll
            for (int mi = 0; mi < 2; mi++)
#pragma unroll
                for (int p = 0; p < 2; p++) {
                    mma16816(acc[mi][2 * p],     ah[mi], &bh[p][0]);
                    mma16816(acc[mi][2 * p + 1], ah[mi], &bh[p][2]);
                }
        }
    };

    // --- full epilogue for special tiles e in {0, 64} and the tail ---
    auto do_epi_full = [&](int e, float (&acc)[2][4][4]) {
        const int j = (bid + e) & 127;
        if ((e == 0) | (e == 64)) {
            const bool isdiag = (e == 0);
#pragma unroll
            for (int mi = 0; mi < 2; mi++)
#pragma unroll
                for (int rh = 0; rh < 2; rh++) {
                    const int r_l = wy * 32 + mi * 16 + rh * 8 + (lane >> 2);
#pragma unroll
                    for (int nj = 0; nj < 4; nj++)
#pragma unroll
                        for (int jj = 0; jj < 2; jj++) {
                            float& v = acc[mi][nj][rh * 2 + jj];
                            const int c_l = wx * 32 + nj * 8 + ((lane & 3) << 1) + jj;
                            if (c_l == r_l) {
                                if (isdiag) v = MASKV;
                                else {
                                    g_pos[(bid << 7) + r_l] = v;
                                    g_pos[(j << 7) + r_l]   = v;
                                }
                            }
                        }
                }
        }
#pragma unroll
        for (int ri = 0; ri < 4; ri++) row_chunk(ri, acc);
        if (e != 0) {
            const int slotRow = (((j * 65 + e) << 2) + wy) * 64;
#pragma unroll
            for (int nj = 0; nj < 4; nj++) col_chunk(nj, acc, slotRow);
        }
    };

    // --- interleaved: MMAs of tile i + epilogue chunks of tile i-1 ---
    auto do_tile = [&](int i, float (&accC)[2][4][4], float (&accP)[2][4][4]) {
        const uint32_t bbuf = b_base + ((uint32_t)(i & 1) << 15);
        const int e = i - 1;
        const int j = (bid + e) & 127;
        const int slotRow = (((j * 65 + e) << 2) + wy) * 64;
#pragma unroll
        for (int mi = 0; mi < 2; mi++)
#pragma unroll
            for (int nj = 0; nj < 4; nj++)
#pragma unroll
                for (int k = 0; k < 4; k++) accC[mi][nj][k] = 0.0f;
#pragma unroll
        for (int kc = 0; kc < 8; kc++) {
            const uint32_t akx = ((uint32_t)(kc << 5) + a_koff) ^ a_swz;
            const uint32_t bkx = ((uint32_t)(kc << 5) + b_koff) ^ b_swz;
            uint32_t ah[2][4], bh[2][4];
#pragma unroll
            for (int mi = 0; mi < 2; mi++)
                ldmx4(ah[mi], a_base + (uint32_t)(mi << 12) + akx);
#pragma unroll
            for (int p = 0; p < 2; p++)
                ldmx4(bh[p], bbuf + (uint32_t)(p << 12) + bkx);
#pragma unroll
            for (int mi = 0; mi < 2; mi++)
#pragma unroll
                for (int p = 0; p < 2; p++) {
                    mma16816(accC[mi][2 * p],     ah[mi], &bh[p][0]);
                    mma16816(accC[mi][2 * p + 1], ah[mi], &bh[p][2]);
                }
            if (kc < 4) col_chunk(kc, accP, slotRow);  // under tensor shadow
            else        row_chunk(kc - 4, accP);
        }
    };

    // --- prefetch/visibility handshake ---
    auto handshake = [&](int i) {
        __syncthreads();                       // buffer (i+1)&1 free of readers
        if (i < dmax) {
            load_tile(sbase + B_OFF + (uint32_t)(((i + 1) & 1) << 15),
                      ((bid + i + 1) & 127) << 7, tid);
            CP_COMMIT();
            CP_WAIT1();
        } else {
            CP_WAIT0();
        }
        __syncthreads();                       // tile i visible to all warps
    };

    handshake(0); do_mma(0, acc0);
    handshake(1); do_mma(1, acc1); do_epi_full(0, acc0);
    for (int d = 2; d + 1 <= dmax; d += 2) {
        handshake(d);     do_tile(d,     acc0, acc1);
        handshake(d + 1); do_tile(d + 1, acc1, acc0);
    }
    if (dmax == 64) {
        handshake(64); do_tile(64, acc0, acc1);
        do_epi_full(64, acc0);
    } else {
        do_epi_full(63, acc1);
    }

    // --- merge row state across the 4 lanes sharing each row, write g_rp ----
#pragma unroll
    for (int off = 1; off <= 2; off <<= 1)
#pragma unroll
        for (int ri = 0; ri < 4; ri++) {
            const float om = __shfl_xor_sync(0xffffffffu, m[ri], off);
            const float os = __shfl_xor_sync(0xffffffffu, s[ri], off);
            msmerge(m[ri], s[ri], om, os);
        }
    if ((lane & 3) == 0) {
#pragma unroll
        for (int mi = 0; mi < 2; mi++)
#pragma unroll
            for (int rh = 0; rh < 2; rh++) {
                const int r_l = wy * 32 + mi * 16 + rh * 8 + (lane >> 2);
                sm_m[wx][r_l] = m[mi * 2 + rh];
                sm_s[wx][r_l] = s[mi * 2 + rh];
            }
    }
    __syncthreads();
    if (tid < 128) {
        float mm = sm_m[0][tid], ss = sm_s[0][tid];
        msmerge(mm, ss, sm_m[1][tid], sm_s[1][tid]);
        float m2 = sm_m[2][tid], s2 = sm_s[2][tid];
        msmerge(m2, s2, sm_m[3][tid], sm_s[3][tid]);
        msmerge(mm, ss, m2, s2);
        g_rp[(bid << 7) + tid] = make_float2(mm, ss);
    }
}

// ---------------------------------------------------------------------------
__global__ __launch_bounds__(128) void simclr_merge() {
    __shared__ float red[4];
    const int r   = blockIdx.x;
    const int k   = threadIdx.x;
    const int dmx = (r >= 64) ? 64 : 63;
    const int pr  = k >> 1;
    const int hi  = k & 1;

    float mm[4], ss[4];
#pragma unroll
    for (int w = 0; w < 4; w++) {
        const uint2 p = g_cph[(((r * 65 + 1) << 2) + w) * 64 + pr];
        mm[w] = hi ? h2_hi(p.x) : h2_lo(p.x);
        ss[w] = hi ? h2_hi(p.y) : h2_lo(p.y);
    }
    for (int d = 2; d <= dmx; d++) {
#pragma unroll
        for (int w = 0; w < 4; w++) {
            const uint2 p = g_cph[(((r * 65 + d) << 2) + w) * 64 + pr];
            const float pm = hi ? h2_hi(p.x) : h2_lo(p.x);
            const float ps = hi ? h2_hi(p.y) : h2_lo(p.y);
            msmerge(mm[w], ss[w], pm, ps);
        }
    }
    msmerge(mm[0], ss[0], mm[1], ss[1]);
    msmerge(mm[2], ss[2], mm[3], ss[3]);
    msmerge(mm[0], ss[0], mm[2], ss[2]);
    const float2 rp = g_rp[(r << 7) + k];
    msmerge(mm[0], ss[0], rp.x, rp.y);

    const float LN2   = 0.6931471805599453f;
    const float INV_T = 14.285714285714286f;
    const float lse   = (mm[0] + log2f(ss[0])) * LN2;
    float term = lse - g_pos[(r << 7) + k] * INV_T;
#pragma unroll
    for (int off = 16; off; off >>= 1)
        term += __shfl_xor_sync(0xffffffffu, term, off);
    if ((k & 31) == 0) red[k >> 5] = term;
    __syncthreads();
    if (k == 0) g_partials[r] = red[0] + red[1] + red[2] + red[3];
}

__global__ void simclr_final(float* __restrict__ out) {
    __shared__ float red[NBLK];
    red[threadIdx.x] = g_partials[threadIdx.x];
    __syncthreads();
    for (int off = NBLK / 2; off; off >>= 1) {
        if (threadIdx.x < off) red[threadIdx.x] += red[threadIdx.x + off];
        __syncthreads();
    }
    if (threadIdx.x == 0) out[0] = red[0] * (1.0f / (float)NTOT);
}

extern "C" void kernel_launch(void* const* d_in, const int* in_sizes, int n_in,
                              void* d_out, int out_size) {
    const float* fo = (const float*)d_in[0];
    const float* fa = (const float*)d_in[1];
    float* out = (float*)d_out;

    cudaFuncSetAttribute(simclr_mma, cudaFuncAttributeMaxDynamicSharedMemorySize, SMEM_DYN);

    pack_kernel<<<NTOT * 128 / 4 / 256, 256>>>(fo, fa);
    simclr_mma<<<NBLK, THREADS, SMEM_DYN>>>();
    simclr_merge<<<NBLK, 128>>>();
    simclr_final<<<1, NBLK>>>(out);
}

// round 10
// speedup vs baseline: 28.6654x; 1.0211x over previous
#include <cuda_runtime.h>
#include <cuda_fp16.h>
#include <math.h>
#include <stdint.h>

// ===========================================================================
// SimCLR loss, symmetry-halved HMMA GEMM + two-sided online logsumexp.
// 512 threads / 16 warps (4x4 grid, 32x32 warp tiles). This round:
//  - explicit A/B fragment double-buffering (LDSM of chunk k+1 issued before
//    MMAs of chunk k) to overlap smem crossbar with tensor pipe,
//  - warp phase rotation (wx parity) to deconvoy crossbar demand,
//  - 4-deep cp.async B ring -> ONE __syncthreads per tile.
// Epilogue of tile d-1 interleaved into tile d's chunk loop (col chunks on
// kc 0-3, row chunks on kc 4-7), f16x2-packed column reductions.
// Pure fp16 single-term D = Ahi*Bhi^T (loss rel_err ~8e-7).
// Baseline ISA only (compute_103: no tcgen05/TMA).
// ===========================================================================

#define BHALF   8192
#define NTOT    16384
#define NBLK    128
#define THREADS 512

#define B_OFF   32768
#define SMEM_DYN (B_OFF + 4 * 32768)     // 163840

__device__ __align__(16) __half g_hi[NTOT * 128];
__device__ uint2  g_cph[128 * 65 * 4 * 64];   // [j][d][wy][colpair] (m.h2, s.h2)
__device__ float2 g_rp[NTOT];
__device__ float  g_pos[NTOT];
__device__ float  g_partials[NBLK];

// ---------------------------------------------------------------------------
static __device__ __forceinline__ uint32_t smem_u32(const void* p) {
    uint32_t a;
    asm("{ .reg .u64 t; cvta.to.shared.u64 t, %1; cvt.u32.u64 %0, t; }"
        : "=r"(a) : "l"(p));
    return a;
}
static __device__ __forceinline__ float ex2f(float x) {
    float r; asm("ex2.approx.ftz.f32 %0, %1;" : "=f"(r) : "f"(x)); return r;
}
static __device__ __forceinline__ void ldmx4(uint32_t* r, uint32_t addr) {
    asm volatile("ldmatrix.sync.aligned.m8n8.x4.shared.b16 {%0,%1,%2,%3}, [%4];"
                 : "=r"(r[0]), "=r"(r[1]), "=r"(r[2]), "=r"(r[3]) : "r"(addr));
}
static __device__ __forceinline__ void mma16816(float* c, const uint32_t* a,
                                                const uint32_t* b) {
    asm volatile(
        "mma.sync.aligned.m16n8k16.row.col.f32.f16.f16.f32 "
        "{%0,%1,%2,%3}, {%4,%5,%6,%7}, {%8,%9}, {%0,%1,%2,%3};"
        : "+f"(c[0]), "+f"(c[1]), "+f"(c[2]), "+f"(c[3])
        : "r"(a[0]), "r"(a[1]), "r"(a[2]), "r"(a[3]), "r"(b[0]), "r"(b[1]));
}
static __device__ __forceinline__ void msmerge(float& m, float& s, float om, float os) {
    float dm = m - om;
    float e  = ex2f(-fabsf(dm));
    s = (dm >= 0.0f) ? fmaf(os, e, s) : fmaf(s, e, os);
    m = fmaxf(m, om);
}
static __device__ __forceinline__ uint32_t pack_h2(float lo, float hi) {
    uint32_t r; asm("cvt.rn.f16x2.f32 %0, %1, %2;" : "=r"(r) : "f"(hi), "f"(lo)); return r;
}
static __device__ __forceinline__ uint32_t hmax2u(uint32_t a, uint32_t b) {
    uint32_t r; asm("max.f16x2 %0, %1, %2;" : "=r"(r) : "r"(a), "r"(b)); return r;
}
static __device__ __forceinline__ uint32_t hadd2u(uint32_t a, uint32_t b) {
    uint32_t r; asm("add.rn.f16x2 %0, %1, %2;" : "=r"(r) : "r"(a), "r"(b)); return r;
}
static __device__ __forceinline__ float h2_lo(uint32_t u) {
    float f; asm("{ .reg .b16 l,h; mov.b32 {l,h}, %1; cvt.f32.f16 %0, l; }"
                 : "=f"(f) : "r"(u)); return f;
}
static __device__ __forceinline__ float h2_hi(uint32_t u) {
    float f; asm("{ .reg .b16 l,h; mov.b32 {l,h}, %1; cvt.f32.f16 %0, h; }"
                 : "=f"(f) : "r"(u)); return f;
}
#define CP_ASYNC16(dst, src) \
    asm volatile("cp.async.cg.shared.global [%0], [%1], 16;" :: "r"(dst), "l"(src) : "memory")
#define CP_COMMIT() asm volatile("cp.async.commit_group;" ::: "memory")
#define CP_WAIT2()  asm volatile("cp.async.wait_group 2;" ::: "memory")

static __device__ __forceinline__ void load_tile(uint32_t dstBase, int row0, int tid) {
    const char* hb = (const char*)g_hi + (size_t)row0 * 256;
#pragma unroll
    for (int j = 0; j < 4; j++) {
        int q   = tid + j * THREADS;          // 0..2047
        int row = q >> 4;
        int c16 = q & 15;
        uint32_t dst = dstBase + (uint32_t)(row << 8)
                     + (uint32_t)((c16 ^ (row & 7)) << 4);
        CP_ASYNC16(dst, hb + row * 256 + c16 * 16);
    }
}

// ---------------------------------------------------------------------------
__global__ void pack_kernel(const float* __restrict__ fo, const float* __restrict__ fa) {
    int idx4 = blockIdx.x * blockDim.x + threadIdx.x;
    int row  = idx4 >> 5;
    const float* src = (row < BHALF) ? fo : fa;
    int lrow = (row < BHALF) ? row : row - BHALF;
    float4 v = reinterpret_cast<const float4*>(src)[(lrow << 5) + (idx4 & 31)];
    ushort4 h4;
    h4.x = __half_as_ushort(__float2half_rn(v.x));
    h4.y = __half_as_ushort(__float2half_rn(v.y));
    h4.z = __half_as_ushort(__float2half_rn(v.z));
    h4.w = __half_as_ushort(__float2half_rn(v.w));
    reinterpret_cast<ushort4*>(g_hi)[idx4] = h4;
}

// ---------------------------------------------------------------------------
__global__ __launch_bounds__(THREADS, 1) void simclr_mma() {
    extern __shared__ __align__(1024) char dynsm[];
    __shared__ float sm_m[4][128], sm_s[4][128];

    const uint32_t sbase = smem_u32(dynsm);
    const int tid  = threadIdx.x;
    const int wid  = tid >> 5;
    const int lane = tid & 31;
    const int wy   = wid & 3;    // M group (32 rows); also SMSP id
    const int wx   = wid >> 2;   // N group (32 cols)
    const int bid  = blockIdx.x;
    const int r0   = bid * 128;
    const int dmax = (bid < 64) ? 64 : 63;
    const int ph   = (wx & 1) << 2;           // chunk phase 0 or 4 (deconvoy)

    const uint32_t a_row  = (uint32_t)(wy * 32 + (lane & 15));
    const uint32_t a_base = sbase + (a_row << 8);
    const uint32_t a_swz  = (a_row & 7) << 4;
    const uint32_t a_koff = (lane >> 4) << 4;

    const uint32_t b_row  = (uint32_t)(wx * 32 + ((lane >> 4) << 3) + (lane & 7));
    const uint32_t b_base = sbase + B_OFF + (b_row << 8);
    const uint32_t b_swz  = (b_row & 7) << 4;
    const uint32_t b_koff = ((lane >> 3) & 1) << 4;

    const float C2    = 20.609929155556627f;   // (1/0.07)*log2(e)
    const float MASKV = -3.0e28f;

    float m[4], s[4];
#pragma unroll
    for (int i = 0; i < 4; i++) { m[i] = -1e30f; s[i] = 0.0f; }

    float acc0[2][4][4], acc1[2][4][4];

    // --- column chunk: one nj (8 cols = 4 pairs), f16x2 cross-lane reduce ---
    auto col_chunk = [&](int nj, const float (&acc)[2][4][4], int slotRow) {
        const float v00 = acc[0][nj][0], v01 = acc[0][nj][2];
        const float v02 = acc[1][nj][0], v03 = acc[1][nj][2];
        const float v10 = acc[0][nj][1], v11 = acc[0][nj][3];
        const float v12 = acc[1][nj][1], v13 = acc[1][nj][3];
        const float mx0 = fmaxf(fmaxf(v00, v01), fmaxf(v02, v03)) * C2;
        const float mx1 = fmaxf(fmaxf(v10, v11), fmaxf(v12, v13)) * C2;
        uint32_t m2 = pack_h2(mx0, mx1);
        m2 = hmax2u(m2, __shfl_xor_sync(0xffffffffu, m2, 4));
        m2 = hmax2u(m2, __shfl_xor_sync(0xffffffffu, m2, 8));
        m2 = hmax2u(m2, __shfl_xor_sync(0xffffffffu, m2, 16));
        const float m0 = h2_lo(m2), m1 = h2_hi(m2);
        float s0 = ex2f(fmaf(v00, C2, -m0)) + ex2f(fmaf(v01, C2, -m0))
                 + ex2f(fmaf(v02, C2, -m0)) + ex2f(fmaf(v03, C2, -m0));
        float s1 = ex2f(fmaf(v10, C2, -m1)) + ex2f(fmaf(v11, C2, -m1))
                 + ex2f(fmaf(v12, C2, -m1)) + ex2f(fmaf(v13, C2, -m1));
        uint32_t s2 = pack_h2(s0, s1);
        s2 = hadd2u(s2, __shfl_xor_sync(0xffffffffu, s2, 4));
        s2 = hadd2u(s2, __shfl_xor_sync(0xffffffffu, s2, 8));
        s2 = hadd2u(s2, __shfl_xor_sync(0xffffffffu, s2, 16));
        if (lane < 4)
            g_cph[slotRow + wx * 16 + nj * 4 + lane] = make_uint2(m2, s2);
    };

    // --- row chunk: guarded online LSE update for one ri ---
    auto row_chunk = [&](int ri, const float (&acc)[2][4][4]) {
        const int mi = ri >> 1, rh = ri & 1;
        float mxr = acc[mi][0][rh * 2];
#pragma unroll
        for (int nj = 0; nj < 4; nj++) {
            mxr = fmaxf(mxr, acc[mi][nj][rh * 2]);
            mxr = fmaxf(mxr, acc[mi][nj][rh * 2 + 1]);
        }
        const float mx2 = mxr * C2;
        if (mx2 > m[ri] - 30.0f) {
            const float nm = fmaxf(m[ri], mx2);
            float a0 = 0.0f;
#pragma unroll
            for (int nj = 0; nj < 4; nj++) {
                a0 += ex2f(fmaf(acc[mi][nj][rh * 2],     C2, -nm));
                a0 += ex2f(fmaf(acc[mi][nj][rh * 2 + 1], C2, -nm));
            }
            s[ri] = s[ri] * ex2f(m[ri] - nm) + a0;
            m[ri] = nm;
        }
    };

    // --- fragment load for chunk kk (phase-rotated index) ---
    auto ldfrag = [&](int kk, uint32_t (&ah)[2][4], uint32_t (&bh)[2][4],
                      uint32_t bbuf) {
        const uint32_t akx = ((uint32_t)(kk << 5) + a_koff) ^ a_swz;
        const uint32_t bkx = ((uint32_t)(kk << 5) + b_koff) ^ b_swz;
        ldmx4(ah[0], a_base + akx);
        ldmx4(ah[1], a_base + 4096u + akx);
        ldmx4(bh[0], bbuf + bkx);
        ldmx4(bh[1], bbuf + 4096u + bkx);
    };
    auto mmachunk = [&](float (&acc)[2][4][4], const uint32_t (&ah)[2][4],
                        const uint32_t (&bh)[2][4]) {
#pragma unroll
        for (int mi = 0; mi < 2; mi++)
#pragma unroll
            for (int p = 0; p < 2; p++) {
                mma16816(acc[mi][2 * p],     ah[mi], &bh[p][0]);
                mma16816(acc[mi][2 * p + 1], ah[mi], &bh[p][2]);
            }
    };

    // --- tile i: frag-pipelined MMAs + interleaved epilogue of tile e ---
    auto do_tile = [&](int i, int e, float (&accC)[2][4][4],
                       float (&accP)[2][4][4]) {
        const uint32_t bbuf = b_base + ((uint32_t)(i & 3) << 15);
        const bool epi = (e >= 1);
        int slotRow = 0;
        if (epi) {
            const int j = (bid + e) & 127;
            slotRow = (((j * 65 + e) << 2) + wy) * 64;
        }
#pragma unroll
        for (int mi = 0; mi < 2; mi++)
#pragma unroll
            for (int nj = 0; nj < 4; nj++)
#pragma unroll
                for (int k = 0; k < 4; k++) accC[mi][nj][k] = 0.0f;

        uint32_t ahA[2][4], bhA[2][4], ahB[2][4], bhB[2][4];
        ldfrag(ph, ahA, bhA, bbuf);
#pragma unroll
        for (int kc = 0; kc < 8; kc++) {
            if ((kc & 1) == 0) {
                if (kc < 7) ldfrag((kc + 1 + ph) & 7, ahB, bhB, bbuf);
                mmachunk(accC, ahA, bhA);
            } else {
                if (kc < 7) ldfrag((kc + 1 + ph) & 7, ahA, bhA, bbuf);
                mmachunk(accC, ahB, bhB);
            }
            if (epi) {
                if (kc < 4) col_chunk(kc, accP, slotRow);
                else        row_chunk(kc - 4, accP);
            }
        }
    };

    // --- full epilogue for special tiles e in {0, 64} and the tail ---
    auto do_epi_full = [&](int e, float (&acc)[2][4][4]) {
        const int j = (bid + e) & 127;
        if ((e == 0) | (e == 64)) {
            const bool isdiag = (e == 0);
#pragma unroll
            for (int mi = 0; mi < 2; mi++)
#pragma unroll
                for (int rh = 0; rh < 2; rh++) {
                    const int r_l = wy * 32 + mi * 16 + rh * 8 + (lane >> 2);
#pragma unroll
                    for (int nj = 0; nj < 4; nj++)
#pragma unroll
                        for (int jj = 0; jj < 2; jj++) {
                            float& v = acc[mi][nj][rh * 2 + jj];
                            const int c_l = wx * 32 + nj * 8 + ((lane & 3) << 1) + jj;
                            if (c_l == r_l) {
                                if (isdiag) v = MASKV;
                                else {
                                    g_pos[(bid << 7) + r_l] = v;
                                    g_pos[(j << 7) + r_l]   = v;
                                }
                            }
                        }
                }
        }
#pragma unroll
        for (int ri = 0; ri < 4; ri++) row_chunk(ri, acc);
        if (e != 0) {
            const int slotRow = (((j * 65 + e) << 2) + wy) * 64;
#pragma unroll
            for (int nj = 0; nj < 4; nj++) col_chunk(nj, acc, slotRow);
        }
    };

    // --- per-tile pre-step: prefetch i+2, wait for tile i, ONE barrier ---
    auto do_pre = [&](int i) {
        if (i + 2 <= dmax)
            load_tile(sbase + B_OFF + ((uint32_t)((i + 2) & 3) << 15),
                      ((bid + i + 2) & 127) << 7, tid);
        CP_COMMIT();
        CP_WAIT2();
        __syncthreads();
    };

    // Prologue: A + B0 in group0, B1 in group1
    load_tile(sbase, r0, tid);
    load_tile(sbase + B_OFF, r0, tid);
    CP_COMMIT();
    load_tile(sbase + B_OFF + (1u << 15), ((bid + 1) & 127) << 7, tid);
    CP_COMMIT();

    do_pre(0); do_tile(0, -1, acc0, acc1);
    do_pre(1); do_tile(1, -1, acc1, acc0);
    do_epi_full(0, acc0);
    for (int d = 2; d + 1 <= dmax; d += 2) {
        do_pre(d);     do_tile(d,     d - 1, acc0, acc1);
        do_pre(d + 1); do_tile(d + 1, d,     acc1, acc0);
    }
    if (dmax == 64) {
        do_pre(64); do_tile(64, 63, acc0, acc1);
        do_epi_full(64, acc0);
    } else {
        do_epi_full(63, acc1);
    }

    // --- merge row state across the 4 lanes sharing each row, write g_rp ----
#pragma unroll
    for (int off = 1; off <= 2; off <<= 1)
#pragma unroll
        for (int ri = 0; ri < 4; ri++) {
            const float om = __shfl_xor_sync(0xffffffffu, m[ri], off);
            const float os = __shfl_xor_sync(0xffffffffu, s[ri], off);
            msmerge(m[ri], s[ri], om, os);
        }
    if ((lane & 3) == 0) {
#pragma unroll
        for (int mi = 0; mi < 2; mi++)
#pragma unroll
            for (int rh = 0; rh < 2; rh++) {
                const int r_l = wy * 32 + mi * 16 + rh * 8 + (lane >> 2);
                sm_m[wx][r_l] = m[mi * 2 + rh];
                sm_s[wx][r_l] = s[mi * 2 + rh];
            }
    }
    __syncthreads();
    if (tid < 128) {
        float mm = sm_m[0][tid], ss = sm_s[0][tid];
        msmerge(mm, ss, sm_m[1][tid], sm_s[1][tid]);
        float m2 = sm_m[2][tid], s2 = sm_s[2][tid];
        msmerge(m2, s2, sm_m[3][tid], sm_s[3][tid]);
        msmerge(mm, ss, m2, s2);
        g_rp[(bid << 7) + tid] = make_float2(mm, ss);
    }
}

// ---------------------------------------------------------------------------
__global__ __launch_bounds__(128) void simclr_merge() {
    __shared__ float red[4];
    const int r   = blockIdx.x;
    const int k   = threadIdx.x;
    const int dmx = (r >= 64) ? 64 : 63;
    const int pr  = k >> 1;
    const int hi  = k & 1;

    float mm[4], ss[4];
#pragma unroll
    for (int w = 0; w < 4; w++) {
        const uint2 p = g_cph[(((r * 65 + 1) << 2) + w) * 64 + pr];
        mm[w] = hi ? h2_hi(p.x) : h2_lo(p.x);
        ss[w] = hi ? h2_hi(p.y) : h2_lo(p.y);
    }
    for (int d = 2; d <= dmx; d++) {
#pragma unroll
        for (int w = 0; w < 4; w++) {
            const uint2 p = g_cph[(((r * 65 + d) << 2) + w) * 64 + pr];
            const float pm = hi ? h2_hi(p.x) : h2_lo(p.x);
            const float ps = hi ? h2_hi(p.y) : h2_lo(p.y);
            msmerge(mm[w], ss[w], pm, ps);
        }
    }
    msmerge(mm[0], ss[0], mm[1], ss[1]);
    msmerge(mm[2], ss[2], mm[3], ss[3]);
    msmerge(mm[0], ss[0], mm[2], ss[2]);
    const float2 rp = g_rp[(r << 7) + k];
    msmerge(mm[0], ss[0], rp.x, rp.y);

    const float LN2   = 0.6931471805599453f;
    const float INV_T = 14.285714285714286f;
    const float lse   = (mm[0] + log2f(ss[0])) * LN2;
    float term = lse - g_pos[(r << 7) + k] * INV_T;
#pragma unroll
    for (int off = 16; off; off >>= 1)
        term += __shfl_xor_sync(0xffffffffu, term, off);
    if ((k & 31) == 0) red[k >> 5] = term;
    __syncthreads();
    if (k == 0) g_partials[r] = red[0] + red[1] + red[2] + red[3];
}

__global__ void simclr_final(float* __restrict__ out) {
    __shared__ float red[NBLK];
    red[threadIdx.x] = g_partials[threadIdx.x];
    __syncthreads();
    for (int off = NBLK / 2; off; off >>= 1) {
        if (threadIdx.x < off) red[threadIdx.x] += red[threadIdx.x + off];
        __syncthreads();
    }
    if (threadIdx.x == 0) out[0] = red[0] * (1.0f / (float)NTOT);
}

extern "C" void kernel_launch(void* const* d_in, const int* in_sizes, int n_in,
                              void* d_out, int out_size) {
    const float* fo = (const float*)d_in[0];
    const float* fa = (const float*)d_in[1];
    float* out = (float*)d_out;

    cudaFuncSetAttribute(simclr_mma, cudaFuncAttributeMaxDynamicSharedMemorySize, SMEM_DYN);

    pack_kernel<<<NTOT * 128 / 4 / 256, 256>>>(fo, fa);
    simclr_mma<<<NBLK, THREADS, SMEM_DYN>>>();
    simclr_merge<<<NBLK, 128>>>();
    simclr_final<<<1, NBLK>>>(out);
}